// round 11
// baseline (speedup 1.0000x reference)
#include <cuda_runtime.h>
#include <cuda_bf16.h>
#include <mma.h>
#include <math.h>
#include <stdint.h>

using namespace nvcuda;

#define VN 6144
#define VE 24576

// ---------------- fp32 scratch ----------------
#define SZ_UPN  (8192LL*768)
#define SZ_UPE  (32768LL*1536)
#define SZ_STN  (8192LL*768)
#define SZ_STE  (32768LL*1536)
#define SZ_ENCN (6144LL*128)
#define SZ_ENCE (24576LL*128)
#define SZ_PREN (6144LL*256)
#define SZ_PREE (24576LL*384)
#define SZ_HIDN (6144LL*256)
#define SZ_HCMB (6144LL*128)
#define SZ_HIDE (24576LL*384)
#define SZ_XW   (6144LL*512)
#define SZ_R    (24576LL*256)
#define SZ_AGG  (6144LL*256)
#define SZ_HIDU (6144LL*256)
#define SZ_Y    (6144LL*256)
#define SZ_TMP  (32768LL*64)
#define SZ_TQC  (32768LL*64)
#define SZ_LA   (64LL*256*256)
#define SZ_PQ   (64LL*64*128)
#define SZ_HC1  (6144LL*128)
#define SZ_R1   (24576LL*256)
#define SZ_BC   (256LL)

#define OFF_UPN  0LL
#define OFF_UPE  (OFF_UPN+SZ_UPN)
#define OFF_STN  (OFF_UPE+SZ_UPE)
#define OFF_STE  (OFF_STN+SZ_STN)
#define OFF_ENCN (OFF_STE+SZ_STE)
#define OFF_ENCE (OFF_ENCN+SZ_ENCN)
#define OFF_PREN (OFF_ENCE+SZ_ENCE)
#define OFF_PREE (OFF_PREN+SZ_PREN)
#define OFF_HIDN (OFF_PREE+SZ_PREE)
#define OFF_HCMB (OFF_HIDN+SZ_HIDN)
#define OFF_HIDE (OFF_HCMB+SZ_HCMB)
#define OFF_XW   (OFF_HIDE+SZ_HIDE)
#define OFF_R    (OFF_XW+SZ_XW)
#define OFF_AGG  (OFF_R+SZ_R)
#define OFF_HIDU (OFF_AGG+SZ_AGG)
#define OFF_Y    (OFF_HIDU+SZ_HIDU)
#define OFF_TMP  (OFF_Y+SZ_Y)
#define OFF_TQC  (OFF_TMP+SZ_TMP)
#define OFF_LA   (OFF_TQC+SZ_TQC)
#define OFF_PQ   (OFF_LA+SZ_LA)
#define OFF_HC1  (OFF_PQ+SZ_PQ)
#define OFF_R1   (OFF_HC1+SZ_HC1)
#define OFF_BC   (OFF_R1+SZ_R1)
#define TOTAL_F  (OFF_BC+SZ_BC)

__device__ __align__(256) float g_buf[TOTAL_F];

// ---------------- bf16 transposed split-weight arena: [N][K], hi then lo ----------------
#define W_NI1  0LL
#define W_NI2  65536LL
#define W_EI1  98304LL
#define W_AB   327680LL
#define W_SUM  393216LL
#define W_NU1  425984LL
#define W_NU2  524288LL
#define W_NS1  557056LL
#define W_NS2  565248LL
#define W_ES1  569344LL
#define W_ES2  585728LL
#define W_EC   589824LL
#define W_TOT  688128LL
__device__ __align__(256) __nv_bfloat16 g_wb[2 * W_TOT];

// ---------------- segment descriptor ----------------
struct Seg {
    const float* ptr;
    int ld, div, mul, col0, kend;
};

__device__ __forceinline__ uint32_t s2u(const void* p) {
    uint32_t a;
    asm("{ .reg .u64 t; cvta.to.shared.u64 t, %1; cvt.u32.u64 %0, t; }" : "=r"(a) : "l"(p));
    return a;
}

// =====================================================================
// WMMA tensor GEMM: C = act( concat(seg0,seg1)(row-mapped)[128 x K] @ Wt^T + bias + Cin )
// Wt is [N][K] bf16 split (hi/lo). Block tile 128x64, warps 4x2 of 32x32.
// bf16x3: acc += Ah*Bh + Ah*Bl + Al*Bh  (fp32 accumulate). arelu: relu on A load.
// =====================================================================
#define ALD 72
#define CLD 68
__global__ __launch_bounds__(256) void gemm_wm(
    Seg s0, Seg s1,
    const __nv_bfloat16* __restrict__ Wh, const __nv_bfloat16* __restrict__ Wl, int ldw,
    const float* __restrict__ bias, const float* __restrict__ Cin, int ldcin,
    float* __restrict__ C, int K,
    int relu, int odiv, int omul, int ldc, int pmod, int plim, int arelu)
{
    extern __shared__ char smraw[];
    __nv_bfloat16* Ahs = (__nv_bfloat16*)smraw;          // [128][ALD]
    __nv_bfloat16* Als = Ahs + 128 * ALD;
    __nv_bfloat16* Bhs = Als + 128 * ALD;                // [64][ALD]
    __nv_bfloat16* Bls = Bhs + 64 * ALD;
    float* Cs = (float*)smraw;                           // [128][CLD] (reused)
    int t = threadIdx.x;
    int rowBase = blockIdx.y * 128;
    int n0 = blockIdx.x * 64;
    int wid = t >> 5;
    int wm = wid & 3, wn = wid >> 2;

    wmma::fragment<wmma::accumulator, 16, 16, 16, float> acc[2][2];
#pragma unroll
    for (int i = 0; i < 2; i++)
#pragma unroll
        for (int j = 0; j < 2; j++) wmma::fill_fragment(acc[i][j], 0.f);

    for (int k0 = 0; k0 < K; k0 += 64) {
        const Seg* s = (k0 < s0.kend) ? &s0 : &s1;
        const float* abase = s->ptr + (k0 - s->col0);
        __syncthreads();
        for (int idx = t; idx < 2048; idx += 256) {
            int r = idx >> 4, q = idx & 15;
            int grow = rowBase + r;
            int rr = s->div ? (grow / s->div) * s->mul + (grow % s->div) : grow;
            float4 v = *reinterpret_cast<const float4*>(abase + (size_t)rr * s->ld + q * 4);
            if (arelu) {
                v.x = fmaxf(v.x, 0.f); v.y = fmaxf(v.y, 0.f);
                v.z = fmaxf(v.z, 0.f); v.w = fmaxf(v.w, 0.f);
            }
            __nv_bfloat162 h01 = __floats2bfloat162_rn(v.x, v.y);
            __nv_bfloat162 h23 = __floats2bfloat162_rn(v.z, v.w);
            __nv_bfloat162 l01 = __floats2bfloat162_rn(v.x - __low2float(h01), v.y - __high2float(h01));
            __nv_bfloat162 l23 = __floats2bfloat162_rn(v.z - __low2float(h23), v.w - __high2float(h23));
            uint2 uh, ul;
            uh.x = *reinterpret_cast<uint32_t*>(&h01);
            uh.y = *reinterpret_cast<uint32_t*>(&h23);
            ul.x = *reinterpret_cast<uint32_t*>(&l01);
            ul.y = *reinterpret_cast<uint32_t*>(&l23);
            *reinterpret_cast<uint2*>(Ahs + r * ALD + q * 4) = uh;
            *reinterpret_cast<uint2*>(Als + r * ALD + q * 4) = ul;
        }
        for (int idx = t; idx < 512; idx += 256) {
            int n = idx >> 3, cc = idx & 7;
            size_t so = (size_t)(n0 + n) * ldw + k0 + cc * 8;
            *reinterpret_cast<uint4*>(Bhs + n * ALD + cc * 8) =
                *reinterpret_cast<const uint4*>(Wh + so);
            *reinterpret_cast<uint4*>(Bls + n * ALD + cc * 8) =
                *reinterpret_cast<const uint4*>(Wl + so);
        }
        __syncthreads();
#pragma unroll
        for (int kk = 0; kk < 4; kk++) {
            wmma::fragment<wmma::matrix_a, 16, 16, 16, __nv_bfloat16, wmma::row_major> fah[2], fal[2];
#pragma unroll
            for (int mf = 0; mf < 2; mf++) {
                wmma::load_matrix_sync(fah[mf], Ahs + (wm * 32 + mf * 16) * ALD + kk * 16, ALD);
                wmma::load_matrix_sync(fal[mf], Als + (wm * 32 + mf * 16) * ALD + kk * 16, ALD);
            }
#pragma unroll
            for (int nf = 0; nf < 2; nf++) {
                wmma::fragment<wmma::matrix_b, 16, 16, 16, __nv_bfloat16, wmma::col_major> fbh, fbl;
                wmma::load_matrix_sync(fbh, Bhs + (wn * 32 + nf * 16) * ALD + kk * 16, ALD);
                wmma::load_matrix_sync(fbl, Bls + (wn * 32 + nf * 16) * ALD + kk * 16, ALD);
#pragma unroll
                for (int mf = 0; mf < 2; mf++) {
                    wmma::mma_sync(acc[mf][nf], fah[mf], fbh, acc[mf][nf]);
                    wmma::mma_sync(acc[mf][nf], fah[mf], fbl, acc[mf][nf]);
                    wmma::mma_sync(acc[mf][nf], fal[mf], fbh, acc[mf][nf]);
                }
            }
        }
    }
    __syncthreads();
#pragma unroll
    for (int mf = 0; mf < 2; mf++)
#pragma unroll
        for (int nf = 0; nf < 2; nf++)
            wmma::store_matrix_sync(Cs + (wm * 32 + mf * 16) * CLD + wn * 32 + nf * 16,
                                    acc[mf][nf], CLD, wmma::mem_row_major);
    __syncthreads();
    for (int idx = t; idx < 2048; idx += 256) {
        int r = idx >> 4, c4 = (idx & 15) * 4;
        float4 v = *reinterpret_cast<const float4*>(Cs + r * CLD + c4);
        int grow = rowBase + r;
        int col = n0 + c4;
        if (bias) {
            float4 bb = *reinterpret_cast<const float4*>(bias + col);
            v.x += bb.x; v.y += bb.y; v.z += bb.z; v.w += bb.w;
        }
        if (Cin) {
            float4 cc = *reinterpret_cast<const float4*>(Cin + (size_t)grow * ldcin + col);
            v.x += cc.x; v.y += cc.y; v.z += cc.z; v.w += cc.w;
        }
        if (relu) {
            v.x = fmaxf(v.x, 0.f); v.y = fmaxf(v.y, 0.f);
            v.z = fmaxf(v.z, 0.f); v.w = fmaxf(v.w, 0.f);
        }
        if (pmod != 0 && (grow % pmod) >= plim) { v.x = v.y = v.z = v.w = 0.f; }
        int orow = odiv ? (grow / odiv) * omul + (grow % odiv) : grow;
        *reinterpret_cast<float4*>(C + (size_t)orow * ldc + col) = v;
    }
}
#define WM_SMEM ((2 * 128 * ALD + 2 * 64 * ALD) * 2)

// =====================================================================
// WMMA batched GEMM (plan GEMMs): C = alpha * op(A) @ op(B), bf16x3 split.
// =====================================================================
__global__ __launch_bounds__(256) void gemm_bw(
    const float* __restrict__ A, long long Abs, int lda, int aT,
    const float* __restrict__ B, long long Bbs, int ldb, int bT,
    float* __restrict__ C, long long Cbs, int ldc,
    int K, float alpha)
{
    __shared__ __align__(16) char sm[4 * 64 * ALD * 2];
    __nv_bfloat16* Ah = (__nv_bfloat16*)sm;
    __nv_bfloat16* Al = Ah + 64 * ALD;
    __nv_bfloat16* Bh = Al + 64 * ALD;
    __nv_bfloat16* Bl = Bh + 64 * ALD;
    float* Cs = (float*)sm;
    const float* Ab = A + (size_t)blockIdx.z * Abs;
    const float* Bb = B + (size_t)blockIdx.z * Bbs;
    int t = threadIdx.x;
    int m0 = blockIdx.y * 64, n0 = blockIdx.x * 64;
    int wid = t >> 5, wm = wid & 3, wn = wid >> 2;

    wmma::fragment<wmma::accumulator, 16, 16, 16, float> acc[2];
    wmma::fill_fragment(acc[0], 0.f);
    wmma::fill_fragment(acc[1], 0.f);

    for (int k0 = 0; k0 < K; k0 += 64) {
        __syncthreads();
        if (!aT) {
            for (int idx = t; idx < 1024; idx += 256) {
                int r = idx >> 4, q = idx & 15;
                float4 v = *reinterpret_cast<const float4*>(Ab + (size_t)(m0 + r) * lda + k0 + q * 4);
                __nv_bfloat162 h01 = __floats2bfloat162_rn(v.x, v.y);
                __nv_bfloat162 h23 = __floats2bfloat162_rn(v.z, v.w);
                __nv_bfloat162 l01 = __floats2bfloat162_rn(v.x - __low2float(h01), v.y - __high2float(h01));
                __nv_bfloat162 l23 = __floats2bfloat162_rn(v.z - __low2float(h23), v.w - __high2float(h23));
                uint2 uh, ul;
                uh.x = *reinterpret_cast<uint32_t*>(&h01);
                uh.y = *reinterpret_cast<uint32_t*>(&h23);
                ul.x = *reinterpret_cast<uint32_t*>(&l01);
                ul.y = *reinterpret_cast<uint32_t*>(&l23);
                *reinterpret_cast<uint2*>(Ah + r * ALD + q * 4) = uh;
                *reinterpret_cast<uint2*>(Al + r * ALD + q * 4) = ul;
            }
        } else {
            for (int idx = t; idx < 1024; idx += 256) {
                int kk = idx >> 4, r4 = (idx & 15) * 4;
                float4 v = *reinterpret_cast<const float4*>(Ab + (size_t)(k0 + kk) * lda + m0 + r4);
                float vv[4] = {v.x, v.y, v.z, v.w};
#pragma unroll
                for (int j = 0; j < 4; j++) {
                    __nv_bfloat16 h = __float2bfloat16(vv[j]);
                    Ah[(r4 + j) * ALD + kk] = h;
                    Al[(r4 + j) * ALD + kk] = __float2bfloat16(vv[j] - __bfloat162float(h));
                }
            }
        }
        if (bT) {
            for (int idx = t; idx < 1024; idx += 256) {
                int n = idx >> 4, q = idx & 15;
                float4 v = *reinterpret_cast<const float4*>(Bb + (size_t)(n0 + n) * ldb + k0 + q * 4);
                __nv_bfloat162 h01 = __floats2bfloat162_rn(v.x, v.y);
                __nv_bfloat162 h23 = __floats2bfloat162_rn(v.z, v.w);
                __nv_bfloat162 l01 = __floats2bfloat162_rn(v.x - __low2float(h01), v.y - __high2float(h01));
                __nv_bfloat162 l23 = __floats2bfloat162_rn(v.z - __low2float(h23), v.w - __high2float(h23));
                uint2 uh, ul;
                uh.x = *reinterpret_cast<uint32_t*>(&h01);
                uh.y = *reinterpret_cast<uint32_t*>(&h23);
                ul.x = *reinterpret_cast<uint32_t*>(&l01);
                ul.y = *reinterpret_cast<uint32_t*>(&l23);
                *reinterpret_cast<uint2*>(Bh + n * ALD + q * 4) = uh;
                *reinterpret_cast<uint2*>(Bl + n * ALD + q * 4) = ul;
            }
        } else {
            for (int idx = t; idx < 1024; idx += 256) {
                int kk = idx >> 4, n4 = (idx & 15) * 4;
                float4 v = *reinterpret_cast<const float4*>(Bb + (size_t)(k0 + kk) * ldb + n0 + n4);
                float vv[4] = {v.x, v.y, v.z, v.w};
#pragma unroll
                for (int j = 0; j < 4; j++) {
                    __nv_bfloat16 h = __float2bfloat16(vv[j]);
                    Bh[(n4 + j) * ALD + kk] = h;
                    Bl[(n4 + j) * ALD + kk] = __float2bfloat16(vv[j] - __bfloat162float(h));
                }
            }
        }
        __syncthreads();
#pragma unroll
        for (int kk = 0; kk < 4; kk++) {
            wmma::fragment<wmma::matrix_a, 16, 16, 16, __nv_bfloat16, wmma::row_major> fah, fal;
            wmma::load_matrix_sync(fah, Ah + (wm * 16) * ALD + kk * 16, ALD);
            wmma::load_matrix_sync(fal, Al + (wm * 16) * ALD + kk * 16, ALD);
#pragma unroll
            for (int nf = 0; nf < 2; nf++) {
                wmma::fragment<wmma::matrix_b, 16, 16, 16, __nv_bfloat16, wmma::col_major> fbh, fbl;
                wmma::load_matrix_sync(fbh, Bh + (wn * 32 + nf * 16) * ALD + kk * 16, ALD);
                wmma::load_matrix_sync(fbl, Bl + (wn * 32 + nf * 16) * ALD + kk * 16, ALD);
                wmma::mma_sync(acc[nf], fah, fbh, acc[nf]);
                wmma::mma_sync(acc[nf], fah, fbl, acc[nf]);
                wmma::mma_sync(acc[nf], fal, fbh, acc[nf]);
            }
        }
    }
    __syncthreads();
#pragma unroll
    for (int nf = 0; nf < 2; nf++)
        wmma::store_matrix_sync(Cs + (wm * 16) * CLD + wn * 32 + nf * 16,
                                acc[nf], CLD, wmma::mem_row_major);
    __syncthreads();
    float* Cb = C + (size_t)blockIdx.z * Cbs;
    for (int idx = t; idx < 1024; idx += 256) {
        int r = idx >> 4, c4 = (idx & 15) * 4;
        float4 v = *reinterpret_cast<const float4*>(Cs + r * CLD + c4);
        v.x *= alpha; v.y *= alpha; v.z *= alpha; v.w *= alpha;
        *reinterpret_cast<float4*>(Cb + (size_t)(m0 + r) * ldc + n0 + c4) = v;
    }
}

// =====================================================================
// SIMT fused GEMM (one-time prep only)
// =====================================================================
template<int BM>
__global__ __launch_bounds__(256) void gemm_seg(
    Seg s0, Seg s1,
    const float* __restrict__ W, const float* __restrict__ bias,
    float* __restrict__ C, int M, int N, int K, int ldc)
{
    const int RI = BM / 16;
    __shared__ float As[8][BM];
    __shared__ float Bs[8][128];
    int t = threadIdx.x;
    int rowBase = blockIdx.y * BM;
    int nBase   = blockIdx.x * 128;
    int tx = t & 15, ty = t >> 4;

    float acc[RI][8];
#pragma unroll
    for (int i = 0; i < RI; i++)
#pragma unroll
        for (int j = 0; j < 8; j++) acc[i][j] = 0.f;

    for (int k0 = 0; k0 < K; k0 += 8) {
        if (BM == 128 || t < 128) {
            int ar = t >> 1;
            int ak = (t & 1) * 4;
            int grow = rowBase + ar;
            float4 av = make_float4(0.f, 0.f, 0.f, 0.f);
            int gk = k0 + ak;
            const Seg* s = (gk < s0.kend) ? &s0 : &s1;
            if (grow < M && s->ptr) {
                int rr = s->div ? (grow / s->div) * s->mul + (grow % s->div) : grow;
                av = *reinterpret_cast<const float4*>(s->ptr + (size_t)rr * s->ld + (gk - s->col0));
            }
            As[ak + 0][ar] = av.x; As[ak + 1][ar] = av.y;
            As[ak + 2][ar] = av.z; As[ak + 3][ar] = av.w;
        }
        {
            int bk = t >> 5, bn = (t & 31) * 4;
            float4 bv = make_float4(0.f, 0.f, 0.f, 0.f);
            int gn = nBase + bn;
            if (gn < N) bv = *reinterpret_cast<const float4*>(W + (size_t)(k0 + bk) * N + gn);
            *reinterpret_cast<float4*>(&Bs[bk][bn]) = bv;
        }
        __syncthreads();
#pragma unroll
        for (int kk = 0; kk < 8; kk++) {
            float a[RI];
            {
                float4 a0 = *reinterpret_cast<const float4*>(&As[kk][ty * 4]);
                a[0] = a0.x; a[1] = a0.y; a[2] = a0.z; a[3] = a0.w;
                if (BM == 128) {
                    float4 a1 = *reinterpret_cast<const float4*>(&As[kk][64 + ty * 4]);
                    a[4] = a1.x; a[5] = a1.y; a[6] = a1.z; a[7] = a1.w;
                }
            }
            float4 b0 = *reinterpret_cast<const float4*>(&Bs[kk][tx * 4]);
            float4 b1 = *reinterpret_cast<const float4*>(&Bs[kk][64 + tx * 4]);
            float b[8] = {b0.x, b0.y, b0.z, b0.w, b1.x, b1.y, b1.z, b1.w};
#pragma unroll
            for (int i = 0; i < RI; i++)
#pragma unroll
                for (int j = 0; j < 8; j++) acc[i][j] += a[i] * b[j];
        }
        __syncthreads();
    }
#pragma unroll
    for (int i = 0; i < RI; i++) {
        int r;
        if (BM == 128) r = rowBase + ((i < 4) ? (ty * 4 + i) : (64 + ty * 4 + i - 4));
        else           r = rowBase + ty * 4 + i;
        if (r >= M) continue;
        float* crow = C + (size_t)r * ldc;
#pragma unroll
        for (int jj = 0; jj < 2; jj++) {
            int col = nBase + ((jj == 0) ? tx * 4 : 64 + tx * 4);
            if (col >= N) continue;
            float v0 = acc[i][jj * 4 + 0], v1 = acc[i][jj * 4 + 1];
            float v2 = acc[i][jj * 4 + 2], v3 = acc[i][jj * 4 + 3];
            if (bias) {
                float4 bb = *reinterpret_cast<const float4*>(bias + col);
                v0 += bb.x; v1 += bb.y; v2 += bb.z; v3 += bb.w;
            }
            float4 vv; vv.x = v0; vv.y = v1; vv.z = v2; vv.w = v3;
            *reinterpret_cast<float4*>(crow + col) = vv;
        }
    }
}

// =====================================================================
// SIMT batched GEMM (logit GEMMs only — fp32 for Sinkhorn input precision)
// =====================================================================
__global__ __launch_bounds__(256) void gemm_bat(
    const float* __restrict__ A, long long Abs, int lda, int aT,
    const float* __restrict__ B, long long Bbs, int ldb, int bT,
    float* __restrict__ C, long long Cbs, int ldc,
    int M, int N, int K, float alpha)
{
    __shared__ float As[16][128];
    __shared__ float Bs[16][128];
    int t = threadIdx.x;
    int b = blockIdx.z;
    int m0 = blockIdx.y * 128;
    int n0 = blockIdx.x * 128;
    const float* Ab = A + (size_t)b * Abs;
    const float* Bb = B + (size_t)b * Bbs;
    int tx = t & 15, ty = t >> 4;
    float acc[8][8];
#pragma unroll
    for (int i = 0; i < 8; i++)
#pragma unroll
        for (int j = 0; j < 8; j++) acc[i][j] = 0.f;

    for (int k0 = 0; k0 < K; k0 += 16) {
        if (!aT) {
            int r = t >> 1, k4 = (t & 1) * 8;
            float4 v0 = make_float4(0.f,0.f,0.f,0.f), v1 = v0;
            if (m0 + r < M) {
                v0 = *reinterpret_cast<const float4*>(Ab + (size_t)(m0 + r) * lda + k0 + k4);
                v1 = *reinterpret_cast<const float4*>(Ab + (size_t)(m0 + r) * lda + k0 + k4 + 4);
            }
            As[k4+0][r]=v0.x; As[k4+1][r]=v0.y; As[k4+2][r]=v0.z; As[k4+3][r]=v0.w;
            As[k4+4][r]=v1.x; As[k4+5][r]=v1.y; As[k4+6][r]=v1.z; As[k4+7][r]=v1.w;
        } else {
            int kk = t >> 4, r4 = (t & 15) * 8;
            float4 v0 = *reinterpret_cast<const float4*>(Ab + (size_t)(k0 + kk) * lda + m0 + r4);
            float4 v1 = *reinterpret_cast<const float4*>(Ab + (size_t)(k0 + kk) * lda + m0 + r4 + 4);
            *reinterpret_cast<float4*>(&As[kk][r4])     = v0;
            *reinterpret_cast<float4*>(&As[kk][r4 + 4]) = v1;
        }
        if (!bT) {
            int kk = t >> 4, n4 = (t & 15) * 8;
            float4 v0 = make_float4(0.f,0.f,0.f,0.f), v1 = v0;
            if (n0 + n4 < N) {
                v0 = *reinterpret_cast<const float4*>(Bb + (size_t)(k0 + kk) * ldb + n0 + n4);
                v1 = *reinterpret_cast<const float4*>(Bb + (size_t)(k0 + kk) * ldb + n0 + n4 + 4);
            }
            *reinterpret_cast<float4*>(&Bs[kk][n4])     = v0;
            *reinterpret_cast<float4*>(&Bs[kk][n4 + 4]) = v1;
        } else {
            int n = t >> 1, k4 = (t & 1) * 8;
            float4 v0 = make_float4(0.f,0.f,0.f,0.f), v1 = v0;
            if (n0 + n < N) {
                v0 = *reinterpret_cast<const float4*>(Bb + (size_t)(n0 + n) * ldb + k0 + k4);
                v1 = *reinterpret_cast<const float4*>(Bb + (size_t)(n0 + n) * ldb + k0 + k4 + 4);
            }
            Bs[k4+0][n]=v0.x; Bs[k4+1][n]=v0.y; Bs[k4+2][n]=v0.z; Bs[k4+3][n]=v0.w;
            Bs[k4+4][n]=v1.x; Bs[k4+5][n]=v1.y; Bs[k4+6][n]=v1.z; Bs[k4+7][n]=v1.w;
        }
        __syncthreads();
#pragma unroll
        for (int kk = 0; kk < 16; kk++) {
            float4 a0 = *reinterpret_cast<const float4*>(&As[kk][ty * 4]);
            float4 a1 = *reinterpret_cast<const float4*>(&As[kk][64 + ty * 4]);
            float4 b0 = *reinterpret_cast<const float4*>(&Bs[kk][tx * 4]);
            float4 b1 = *reinterpret_cast<const float4*>(&Bs[kk][64 + tx * 4]);
            float a[8] = {a0.x,a0.y,a0.z,a0.w,a1.x,a1.y,a1.z,a1.w};
            float bb[8] = {b0.x,b0.y,b0.z,b0.w,b1.x,b1.y,b1.z,b1.w};
#pragma unroll
            for (int i = 0; i < 8; i++)
#pragma unroll
                for (int j = 0; j < 8; j++) acc[i][j] += a[i] * bb[j];
        }
        __syncthreads();
    }
    float* Cb = C + (size_t)b * Cbs;
#pragma unroll
    for (int i = 0; i < 8; i++) {
        int row = (i < 4) ? (ty * 4 + i) : (64 + ty * 4 + i - 4);
        if (m0 + row >= M) continue;
#pragma unroll
        for (int jj = 0; jj < 2; jj++) {
            int col = (jj == 0) ? tx * 4 : 64 + tx * 4;
            if (n0 + col >= N) continue;
            float4 vv;
            vv.x = alpha * acc[i][jj*4+0]; vv.y = alpha * acc[i][jj*4+1];
            vv.z = alpha * acc[i][jj*4+2]; vv.w = alpha * acc[i][jj*4+3];
            *reinterpret_cast<float4*>(Cb + (size_t)(m0 + row) * ldc + n0 + col) = vv;
        }
    }
}

// ---------------- weight prep: transpose + bf16 hi/lo split ----------------
__global__ void tsplit(const float* __restrict__ W, int K, int N,
                       __nv_bfloat16* __restrict__ Dh, __nv_bfloat16* __restrict__ Dl) {
    int gid = blockIdx.x * 256 + threadIdx.x;
    if (gid >= K * N) return;
    int k = gid / N, n = gid % N;
    float v = W[gid];
    __nv_bfloat16 h = __float2bfloat16(v);
    Dh[(size_t)n * K + k] = h;
    Dl[(size_t)n * K + k] = __float2bfloat16(v - __bfloat162float(h));
}
__global__ void tssum(const float* __restrict__ msgW,
                      __nv_bfloat16* __restrict__ Dh, __nv_bfloat16* __restrict__ Dl) {
    int gid = blockIdx.x * 256 + threadIdx.x;
    int k = gid >> 8, n = gid & 255;
    float v = msgW[k * 256 + n] + msgW[(128 + k) * 256 + n];
    __nv_bfloat16 h = __float2bfloat16(v);
    Dh[(size_t)n * 128 + k] = h;
    Dl[(size_t)n * 128 + k] = __float2bfloat16(v - __bfloat162float(h));
}
// fold: W_EC[n][k] = sum_j eiW2[k][j] * msgW3[j][n]  (k<384, j<128, n<256)
//       bc[n] = eiB2 . msgW3[:,n] + msgB[n]
__global__ void fold_ec(const float* __restrict__ eiW2, const float* __restrict__ eiB2,
                        const float* __restrict__ msgW3, const float* __restrict__ msgB,
                        __nv_bfloat16* __restrict__ Dh, __nv_bfloat16* __restrict__ Dl,
                        float* __restrict__ bc) {
    int gid = blockIdx.x * 256 + threadIdx.x;   // 384*256
    if (gid >= 384 * 256) return;
    int k = gid >> 8, n = gid & 255;
    float s = 0.f;
    for (int j = 0; j < 128; j++)
        s += eiW2[k * 128 + j] * msgW3[j * 256 + n];
    __nv_bfloat16 h = __float2bfloat16(s);
    Dh[(size_t)n * 384 + k] = h;
    Dl[(size_t)n * 384 + k] = __float2bfloat16(s - __bfloat162float(h));
    if (k == 0) {
        float b = msgB[n];
        for (int j = 0; j < 128; j++) b += eiB2[j] * msgW3[j * 256 + n];
        bc[n] = b;
    }
}

// ---------------- elementwise / scatter ----------------
__device__ __forceinline__ void red_add_v4(float* addr, float4 v) {
    asm volatile("red.global.add.v4.f32 [%0], {%1,%2,%3,%4};"
                 :: "l"(addr), "f"(v.x), "f"(v.y), "f"(v.z), "f"(v.w) : "memory");
}
__global__ void zero_k(float* __restrict__ p, long long n4) {
    long long i = (long long)blockIdx.x * blockDim.x + threadIdx.x;
    long long stride = (long long)gridDim.x * blockDim.x;
    for (; i < n4; i += stride)
        reinterpret_cast<float4*>(p)[i] = make_float4(0.f, 0.f, 0.f, 0.f);
}
__global__ void scatter_agg(const float* __restrict__ XW, const float* __restrict__ R,
                            const int* __restrict__ fi, const int* __restrict__ ti,
                            float* __restrict__ agg) {
    int gid = blockIdx.x * 256 + threadIdx.x;
    int e = gid >> 6, c = (gid & 63) * 4;
    int f = fi[e], t = ti[e];
    float4 x1f = *reinterpret_cast<const float4*>(XW + (size_t)f * 512 + c);
    float4 x2f = *reinterpret_cast<const float4*>(XW + (size_t)f * 512 + 256 + c);
    float4 x1t = *reinterpret_cast<const float4*>(XW + (size_t)t * 512 + c);
    float4 x2t = *reinterpret_cast<const float4*>(XW + (size_t)t * 512 + 256 + c);
    float4 r   = *reinterpret_cast<const float4*>(R + (size_t)e * 256 + c);
    float4 fwd; fwd.x = x1f.x + x2t.x + r.x; fwd.y = x1f.y + x2t.y + r.y;
                fwd.z = x1f.z + x2t.z + r.z; fwd.w = x1f.w + x2t.w + r.w;
    float4 bwd; bwd.x = x1t.x + x2f.x + r.x; bwd.y = x1t.y + x2f.y + r.y;
                bwd.z = x1t.z + x2f.z + r.z; bwd.w = x1t.w + x2f.w + r.w;
    red_add_v4(agg + (size_t)t * 256 + c, fwd);
    red_add_v4(agg + (size_t)f * 256 + c, bwd);
}
__global__ void msgs_k(const float* __restrict__ Y, const float* __restrict__ R,
                       const int* __restrict__ fi, const int* __restrict__ ti,
                       float* __restrict__ upEp) {
    int gid = blockIdx.x * 256 + threadIdx.x;
    int e = gid >> 6, c = (gid & 63) * 4;
    int f = fi[e], t = ti[e];
    float4 yf = *reinterpret_cast<const float4*>(Y + (size_t)f * 256 + c);
    float4 yt = *reinterpret_cast<const float4*>(Y + (size_t)t * 256 + c);
    float4 r  = *reinterpret_cast<const float4*>(R + (size_t)e * 256 + c);
    float4 v;
    v.x = yf.x + yt.x + 2.f * r.x; v.y = yf.y + yt.y + 2.f * r.y;
    v.z = yf.z + yt.z + 2.f * r.z; v.w = yf.w + yt.w + 2.f * r.w;
    int row = (e / 192) * 256 + (e % 192);
    *reinterpret_cast<float4*>(upEp + (size_t)row * 1536 + c) = v;
}

// ---------------- Sinkhorn (probability domain) ----------------
__global__ __launch_bounds__(256) void sink_node(float* __restrict__ la) {
    __shared__ float tile[64][65];
    __shared__ float cinv[64];
    int b = blockIdx.x, t = threadIdx.x;
    const size_t base = (size_t)b * 4096;
    for (int idx = t; idx < 4096; idx += 256)
        tile[idx >> 6][idx & 63] = la[base + idx];
    __syncthreads();
    int w = t >> 5, l = t & 31;
    for (int it = 0; it < 10; it++) {
#pragma unroll
        for (int i = 0; i < 8; i++) {
            int r = w * 8 + i;
            float v0 = tile[r][l], v1 = tile[r][l + 32];
            if (it == 0) {
                float m = fmaxf(v0, v1);
                for (int o = 16; o; o >>= 1) m = fmaxf(m, __shfl_xor_sync(0xffffffffu, m, o));
                v0 = expf(v0 - m); v1 = expf(v1 - m);
            }
            float s = v0 + v1;
            for (int o = 16; o; o >>= 1) s += __shfl_xor_sync(0xffffffffu, s, o);
            float inv = 1.f / s;
            tile[r][l] = v0 * inv; tile[r][l + 32] = v1 * inv;
        }
        __syncthreads();
        if (t < 64) {
            float s = 0.f;
            for (int q = 0; q < 64; q++) s += tile[q][t];
            cinv[t] = 1.f / s;
        }
        __syncthreads();
        for (int idx = t; idx < 4096; idx += 256) {
            int r = idx >> 6, c = idx & 63;
            tile[r][c] *= cinv[c];
        }
        __syncthreads();
    }
    for (int idx = t; idx < 4096; idx += 256)
        la[base + idx] = tile[idx >> 6][idx & 63];
}

// edge: 2-CTA cluster per batch; tile resident in smem for all 10 iters.
__global__ __launch_bounds__(256) __cluster_dims__(2, 1, 1)
void sink_edge(float* __restrict__ la) {
    extern __shared__ float sm[];
    float* tile = sm;                         // [128][256]
    float* ps   = sm + 32768;                 // [2][256]
    int t = threadIdx.x;
    uint32_t rank;
    asm("mov.u32 %0, %%cluster_ctarank;" : "=r"(rank));
    float* g = la + (size_t)(blockIdx.x >> 1) * 65536 + (size_t)rank * 32768;
    for (int idx = t * 4; idx < 32768; idx += 1024)
        *reinterpret_cast<float4*>(tile + idx) = *reinterpret_cast<const float4*>(g + idx);
    __syncthreads();
    int w = t >> 5, l = t & 31;
    for (int it = 0; it < 10; it++) {
#pragma unroll 1
        for (int i = 0; i < 16; i++) {
            int r = w * 16 + i;
            float v[8];
#pragma unroll
            for (int j = 0; j < 8; j++) v[j] = tile[r * 256 + l + 32 * j];
            if (it == 0) {
                float m = v[0];
#pragma unroll
                for (int j = 1; j < 8; j++) m = fmaxf(m, v[j]);
                for (int o = 16; o; o >>= 1) m = fmaxf(m, __shfl_xor_sync(0xffffffffu, m, o));
#pragma unroll
                for (int j = 0; j < 8; j++) v[j] = expf(v[j] - m);
            }
            float s = 0.f;
#pragma unroll
            for (int j = 0; j < 8; j++) s += v[j];
            for (int o = 16; o; o >>= 1) s += __shfl_xor_sync(0xffffffffu, s, o);
            float inv = 1.f / s;
#pragma unroll
            for (int j = 0; j < 8; j++) tile[r * 256 + l + 32 * j] = v[j] * inv;
        }
        __syncthreads();
        float cs = 0.f;
#pragma unroll 8
        for (int r = 0; r < 128; r++) cs += tile[r * 256 + t];
        int par = it & 1;
        ps[par * 256 + t] = cs;
        __syncthreads();
        asm volatile("barrier.cluster.arrive.aligned;" ::: "memory");
        asm volatile("barrier.cluster.wait.aligned;" ::: "memory");
        uint32_t myaddr = s2u(&ps[par * 256 + t]);
        uint32_t paddr;
        asm("mapa.shared::cluster.u32 %0, %1, %2;" : "=r"(paddr) : "r"(myaddr), "r"(rank ^ 1u));
        float pv;
        asm volatile("ld.shared::cluster.f32 %0, [%1];" : "=f"(pv) : "r"(paddr));
        float inv = 1.f / (cs + pv);
#pragma unroll 8
        for (int r = 0; r < 128; r++) tile[r * 256 + t] *= inv;
        __syncthreads();
    }
    for (int idx = t * 4; idx < 32768; idx += 1024)
        *reinterpret_cast<float4*>(g + idx) = *reinterpret_cast<const float4*>(tile + idx);
    asm volatile("barrier.cluster.arrive.aligned;" ::: "memory");
    asm volatile("barrier.cluster.wait.aligned;" ::: "memory");
}
#define SE_SMEM ((32768 + 512) * 4)

__global__ void score_k(const float* __restrict__ upN, const float* __restrict__ pq,
                        float* __restrict__ out) {
    __shared__ float sh[256];
    int b = blockIdx.x;
    float s = 0.f;
    for (int idx = threadIdx.x; idx < 64 * 128; idx += 256) {
        int q = idx >> 7, d = idx & 127;
        float fqv = upN[(size_t)((2 * b) * 64 + q) * 768 + 640 + d];
        float v = fqv - pq[(size_t)(b * 64 + q) * 128 + d];
        s += fmaxf(v, 0.f);
    }
    sh[threadIdx.x] = s;
    __syncthreads();
    for (int o = 128; o; o >>= 1) {
        if (threadIdx.x < o) sh[threadIdx.x] += sh[threadIdx.x + o];
        __syncthreads();
    }
    if (threadIdx.x == 0) out[b] = -sh[0];
}

// ---------------- host helpers ----------------
static inline Seg mkseg(const float* p, int ld, int div, int mul, int col0, int kend) {
    Seg s; s.ptr = p; s.ld = ld; s.div = div; s.mul = mul; s.col0 = col0; s.kend = kend;
    return s;
}
static inline Seg segz() { return mkseg(nullptr, 4, 0, 0, 0, 1 << 30); }

static inline void lwm(Seg a, Seg b, const __nv_bfloat16* wb, long long woff, int ldw,
                       const float* bias, const float* Cin, int ldcin,
                       float* C, int M, int N, int K, int relu,
                       int odiv, int omul, int ldc, int pmod, int plim, int arelu = 0) {
    dim3 g(N / 64, M / 128);
    gemm_wm<<<g, 256, WM_SMEM>>>(a, b, wb + woff, wb + W_TOT + woff, ldw,
                                 bias, Cin, ldcin, C, K, relu, odiv, omul, ldc,
                                 pmod, plim, arelu);
}
static inline void lbat(const float* A, long long Abs, int lda, int aT,
                        const float* B, long long Bbs, int ldb, int bT,
                        float* C, long long Cbs, int ldc,
                        int M, int N, int K, float alpha, int batch) {
    dim3 g((N + 127) / 128, (M + 127) / 128, batch);
    gemm_bat<<<g, 256>>>(A, Abs, lda, aT, B, Bbs, ldb, bT, C, Cbs, ldc, M, N, K, alpha);
}
static inline void lbw(const float* A, long long Abs, int lda, int aT,
                       const float* B, long long Bbs, int ldb, int bT,
                       float* C, long long Cbs, int ldc,
                       int M, int N, int K, float alpha, int batch) {
    dim3 g(N / 64, M / 64, batch);
    gemm_bw<<<g, 256>>>(A, Abs, lda, aT, B, Bbs, ldb, bT, C, Cbs, ldc, K, alpha);
}

extern "C" void kernel_launch(void* const* d_in, const int* in_sizes, int n_in,
                              void* d_out, int out_size) {
    const float* nodef = (const float*)d_in[0];
    const float* edgef = (const float*)d_in[1];
    const int*   fromi = (const int*)d_in[2];
    const int*   toi   = (const int*)d_in[3];
    const float* encnW = (const float*)d_in[4];
    const float* encnB = (const float*)d_in[5];
    const float* enceW = (const float*)d_in[6];
    const float* enceB = (const float*)d_in[7];
    const float* niW1  = (const float*)d_in[8];
    const float* niB1  = (const float*)d_in[9];
    const float* niW2  = (const float*)d_in[10];
    const float* niB2  = (const float*)d_in[11];
    const float* eiW1  = (const float*)d_in[12];
    const float* eiB1  = (const float*)d_in[13];
    const float* eiW2  = (const float*)d_in[14];
    const float* eiB2  = (const float*)d_in[15];
    const float* msgW  = (const float*)d_in[16];
    const float* msgB  = (const float*)d_in[17];
    const float* nuW1  = (const float*)d_in[18];
    const float* nuB1  = (const float*)d_in[19];
    const float* nuW2  = (const float*)d_in[20];
    const float* nuB2  = (const float*)d_in[21];
    const float* nsW1  = (const float*)d_in[22];
    const float* nsB1  = (const float*)d_in[23];
    const float* nsW2  = (const float*)d_in[24];
    const float* nsB2  = (const float*)d_in[25];
    const float* esW1  = (const float*)d_in[26];
    const float* esB1  = (const float*)d_in[27];
    const float* esW2  = (const float*)d_in[28];
    const float* esB2  = (const float*)d_in[29];
    float* out = (float*)d_out;

    float* base;
    cudaGetSymbolAddress((void**)&base, g_buf);
    __nv_bfloat16* wb;
    cudaGetSymbolAddress((void**)&wb, g_wb);
    float* upN  = base + OFF_UPN;
    float* upE  = base + OFF_UPE;
    float* stN  = base + OFF_STN;
    float* stE  = base + OFF_STE;
    float* encN = base + OFF_ENCN;
    float* encE = base + OFF_ENCE;
    float* preN = base + OFF_PREN;
    float* preE = base + OFF_PREE;
    float* hidn = base + OFF_HIDN;
    float* hcmb = base + OFF_HCMB;
    float* hide = base + OFF_HIDE;
    float* XW   = base + OFF_XW;
    float* R    = base + OFF_R;
    float* agg  = base + OFF_AGG;
    float* hidu = base + OFF_HIDU;
    float* Y    = base + OFF_Y;
    float* tmp  = base + OFF_TMP;
    float* tqc  = base + OFF_TQC;
    float* la   = base + OFF_LA;
    float* pq   = base + OFF_PQ;
    float* hcmb1 = base + OFF_HC1;
    float* R1    = base + OFF_R1;
    float* bc    = base + OFF_BC;

    cudaFuncSetAttribute(gemm_wm, cudaFuncAttributeMaxDynamicSharedMemorySize, WM_SMEM);
    cudaFuncSetAttribute(sink_edge, cudaFuncAttributeMaxDynamicSharedMemorySize, SE_SMEM);

    // ---- weight prep (transpose + bf16 split + edge fold) ----
    tsplit<<<256, 256>>>(niW1, 256, 256, wb + W_NI1, wb + W_TOT + W_NI1);
    tsplit<<<128, 256>>>(niW2, 256, 128, wb + W_NI2, wb + W_TOT + W_NI2);
    tsplit<<<576, 256>>>(eiW1, 384, 384, wb + W_EI1, wb + W_TOT + W_EI1);
    tsplit<<<128, 256>>>(msgW, 128, 256, wb + W_AB, wb + W_TOT + W_AB);
    tsplit<<<128, 256>>>(msgW + 128 * 256, 128, 256, wb + W_AB + 32768, wb + W_TOT + W_AB + 32768);
    tssum<<<128, 256>>>(msgW, wb + W_SUM, wb + W_TOT + W_SUM);
    tsplit<<<384, 256>>>(nuW1, 384, 256, wb + W_NU1, wb + W_TOT + W_NU1);
    tsplit<<<128, 256>>>(nuW2, 256, 128, wb + W_NU2, wb + W_TOT + W_NU2);
    tsplit<<<32, 256>>>(nsW1, 128, 64, wb + W_NS1, wb + W_TOT + W_NS1);
    tsplit<<<16, 256>>>(nsW2, 64, 64, wb + W_NS2, wb + W_TOT + W_NS2);
    tsplit<<<64, 256>>>(esW1, 256, 64, wb + W_ES1, wb + W_TOT + W_ES1);
    tsplit<<<16, 256>>>(esW2, 64, 64, wb + W_ES2, wb + W_TOT + W_ES2);
    fold_ec<<<384, 256>>>(eiW2, eiB2, msgW + 256 * 256, msgB,
                          wb + W_EC, wb + W_TOT + W_EC, bc);

    // ---- one-time SIMT prep GEMMs ----
    {
        dim3 g1(1, VN / 64);
        gemm_seg<64><<<g1, 256>>>(mkseg(nodef, 32, 0, 0, 0, 32), segz(), encnW, encnB, encN, VN, 128, 32, 128);
        dim3 g2(1, VE / 64);
        gemm_seg<64><<<g2, 256>>>(mkseg(edgef, 32, 0, 0, 0, 32), segz(), enceW, enceB, encE, VE, 128, 32, 128);
        dim3 g3(2, VN / 64);
        gemm_seg<64><<<g3, 256>>>(mkseg(encN, 128, 0, 0, 0, 128), segz(), niW1, niB1, preN, VN, 256, 128, 256);
        dim3 g4(3, VE / 64);
        gemm_seg<64><<<g4, 256>>>(mkseg(encE, 128, 0, 0, 0, 128), segz(), eiW1, eiB1, preE, VE, 384, 128, 384);
    }

    // ---- k-invariant precomputes: hcmb1, R1 (folded), and the ENTIRE p==1 step ----
    lwm(mkseg(preN, 256, 0, 0, 0, 256), segz(),
        wb, W_NI2, 256, niB2, 0, 0, hcmb1, VN, 128, 256, 0, 0, 0, 128, 0, 0, 1);
    lwm(mkseg(preE, 384, 0, 0, 0, 384), segz(),
        wb, W_EC, 384, bc, 0, 0, R1, VE, 256, 384, 0, 0, 0, 256, 0, 0, 1);
    lwm(mkseg(hcmb1, 128, 0, 0, 0, 128), segz(),
        wb, W_AB, 128, 0, 0, 0, XW, VN, 512, 128, 0, 0, 0, 512, 0, 0);
    zero_k<<<1536, 256>>>(agg, VN * 256 / 4);
    scatter_agg<<<6144, 256>>>(XW, R1, fromi, toi, agg);
    lwm(mkseg(hcmb1, 128, 0, 0, 0, 128), mkseg(agg, 256, 0, 0, 128, 384),
        wb, W_NU1, 384, nuB1, 0, 0, hidu, VN, 256, 384, 1, 0, 0, 256, 0, 0);
    lwm(mkseg(hidu, 256, 0, 0, 0, 256), segz(),
        wb, W_NU2, 256, nuB2, 0, 0, upN + 128, VN, 128, 256, 0, 48, 64, 768, 0, 0);
    lwm(mkseg(upN + 128, 768, 48, 64, 0, 128), segz(),
        wb, W_SUM, 128, 0, 0, 0, Y, VN, 256, 128, 0, 0, 0, 256, 0, 0);
    msgs_k<<<6144, 256>>>(Y, R1, fromi, toi, upE + 256);

    for (int k = 0; k < 3; k++) {
        for (int p = 2; p <= 5; p++) {
            // node combine
            if (k == 0) {
                lwm(mkseg(upN + (size_t)(p - 1) * 128, 768, 48, 64, 0, 128), segz(),
                    wb, W_NI1, 256, niB1, 0, 0, hidn, VN, 256, 128, 1, 0, 0, 256, 0, 0);
            } else {
                lwm(mkseg(upN + (size_t)(p - 1) * 128, 768, 48, 64, 0, 128),
                    mkseg(stN + (size_t)(p - 1) * 128, 768, 48, 64, 128, 256),
                    wb, W_NI1, 256, niB1, 0, 0, hidn, VN, 256, 256, 1, 0, 0, 256, 0, 0);
            }
            lwm(mkseg(hidn, 256, 0, 0, 0, 256), segz(),
                wb, W_NI2, 256, niB2, 0, 0, hcmb, VN, 128, 256, 0, 0, 0, 128, 0, 0);
            // edge combine + folded R (k-invariant at k==0: reuse R1)
            const float* Rp = R1;
            if (k > 0) {
                lwm(mkseg(stE + (size_t)(p - 1) * 256, 1536, 192, 256, 0, 256), segz(),
                    wb, W_EI1 + 128, 384, 0, preE, 384, hide, VE, 384, 256, 1, 0, 0, 384, 0, 0);
                lwm(mkseg(hide, 384, 0, 0, 0, 384), segz(),
                    wb, W_EC, 384, bc, 0, 0, R, VE, 256, 384, 0, 0, 0, 256, 0, 0);
                Rp = R;
            }
            // XW = hcmb @ [W1|W2] ; aggregate
            lwm(mkseg(hcmb, 128, 0, 0, 0, 128), segz(),
                wb, W_AB, 128, 0, 0, 0, XW, VN, 512, 128, 0, 0, 0, 512, 0, 0);
            zero_k<<<1536, 256>>>(agg, VN * 256 / 4);
            scatter_agg<<<6144, 256>>>(XW, Rp, fromi, toi, agg);
            // node update -> upN slot p
            lwm(mkseg(hcmb, 128, 0, 0, 0, 128), mkseg(agg, 256, 0, 0, 128, 384),
                wb, W_NU1, 384, nuB1, 0, 0, hidu, VN, 256, 384, 1, 0, 0, 256, 0, 0);
            lwm(mkseg(hidu, 256, 0, 0, 0, 256), segz(),
                wb, W_NU2, 256, nuB2, 0, 0, upN + (size_t)p * 128,
                VN, 128, 256, 0, 48, 64, 768, 0, 0);
            // Y = h_p @ (W1+W2) ; msgs -> upE slot p
            lwm(mkseg(upN + (size_t)p * 128, 768, 48, 64, 0, 128), segz(),
                wb, W_SUM, 128, 0, 0, 0, Y, VN, 256, 128, 0, 0, 0, 256, 0, 0);
            msgs_k<<<6144, 256>>>(Y, Rp, fromi, toi, upE + (size_t)p * 256);
        }

        // ================= node transport =================
        lwm(mkseg(upN + 640, 768, 0, 0, 0, 128), segz(),
            wb, W_NS1, 128, nsB1, 0, 0, tmp, 8192, 64, 128, 1, 0, 0, 64, 0, 0);
        lwm(mkseg(tmp, 64, 0, 0, 0, 64), segz(),
            wb, W_NS2, 64, nsB2, 0, 0, tqc, 8192, 64, 64, 0, 0, 0, 64, 64, 48);
        lbat(tqc, 8192, 64, 0, tqc + 4096, 8192, 64, 1, la, 4096, 64, 64, 64, 64, 10.0f, 64);
        sink_node<<<64, 256>>>(la);
        if (k < 2) {
            lbw(la, 4096, 64, 0, upN + 49152 + 128, 98304, 768, 0,
                stN + 128, 98304, 768, 64, 512, 64, 1.0f, 64);
            lbw(la, 4096, 64, 1, upN + 128, 98304, 768, 0,
                stN + 49152 + 128, 98304, 768, 64, 512, 64, 1.0f, 64);
        } else {
            lbw(la, 4096, 64, 0, upN + 49152 + 640, 98304, 768, 0,
                pq, 8192, 128, 64, 128, 64, 1.0f, 64);
        }

        // ================= edge transport (dead at k==2) =================
        if (k < 2) {
            lwm(mkseg(upE + 1280, 1536, 0, 0, 0, 256), segz(),
                wb, W_ES1, 256, esB1, 0, 0, tmp, 32768, 64, 256, 1, 0, 0, 64, 0, 0);
            lwm(mkseg(tmp, 64, 0, 0, 0, 64), segz(),
                wb, W_ES2, 64, esB2, 0, 0, tqc, 32768, 64, 64, 0, 0, 0, 64, 256, 192);
            lbat(tqc, 32768, 64, 0, tqc + 16384, 32768, 64, 1, la, 65536, 256,
                 256, 256, 64, 10.0f, 64);
            sink_edge<<<128, 256, SE_SMEM>>>(la);
            lbw(la, 65536, 256, 0, upE + 393216 + 256, 786432, 1536, 0,
                stE + 256, 786432, 1536, 256, 1024, 256, 1.0f, 64);
            lbw(la, 65536, 256, 1, upE + 256, 786432, 1536, 0,
                stE + 393216 + 256, 786432, 1536, 256, 1024, 256, 1.0f, 64);
        }
    }

    score_k<<<64, 256>>>(upN, pq, out);
    (void)in_sizes; (void)n_in; (void)out_size;
}

// round 13
// speedup vs baseline: 1.0215x; 1.0215x over previous
#include <cuda_runtime.h>
#include <cuda_bf16.h>
#include <mma.h>
#include <math.h>
#include <stdint.h>

using namespace nvcuda;

#define VN 6144
#define VE 24576

// ---------------- fp32 scratch ----------------
#define SZ_UPN  (8192LL*768)
#define SZ_UPE  (32768LL*1536)
#define SZ_STN  (8192LL*768)
#define SZ_STE  (32768LL*1536)
#define SZ_ENCN (6144LL*128)
#define SZ_ENCE (24576LL*128)
#define SZ_PREN (6144LL*256)
#define SZ_PREE (24576LL*384)
#define SZ_HIDN (6144LL*256)
#define SZ_HCMB (6144LL*128)
#define SZ_HIDE (24576LL*384)
#define SZ_ECMB (24576LL*128)
#define SZ_XW   (6144LL*512)
#define SZ_R    (24576LL*256)
#define SZ_AGG  (6144LL*256)
#define SZ_HIDU (6144LL*256)
#define SZ_Y    (6144LL*256)
#define SZ_TMP  (32768LL*64)
#define SZ_TQC  (32768LL*64)
#define SZ_LA   (64LL*256*256)
#define SZ_PQ   (64LL*64*128)
#define SZ_HC1  (6144LL*128)
#define SZ_R1   (24576LL*256)

#define OFF_UPN  0LL
#define OFF_UPE  (OFF_UPN+SZ_UPN)
#define OFF_STN  (OFF_UPE+SZ_UPE)
#define OFF_STE  (OFF_STN+SZ_STN)
#define OFF_ENCN (OFF_STE+SZ_STE)
#define OFF_ENCE (OFF_ENCN+SZ_ENCN)
#define OFF_PREN (OFF_ENCE+SZ_ENCE)
#define OFF_PREE (OFF_PREN+SZ_PREN)
#define OFF_HIDN (OFF_PREE+SZ_PREE)
#define OFF_HCMB (OFF_HIDN+SZ_HIDN)
#define OFF_HIDE (OFF_HCMB+SZ_HCMB)
#define OFF_ECMB (OFF_HIDE+SZ_HIDE)
#define OFF_XW   (OFF_ECMB+SZ_ECMB)
#define OFF_R    (OFF_XW+SZ_XW)
#define OFF_AGG  (OFF_R+SZ_R)
#define OFF_HIDU (OFF_AGG+SZ_AGG)
#define OFF_Y    (OFF_HIDU+SZ_HIDU)
#define OFF_TMP  (OFF_Y+SZ_Y)
#define OFF_TQC  (OFF_TMP+SZ_TMP)
#define OFF_LA   (OFF_TQC+SZ_TQC)
#define OFF_PQ   (OFF_LA+SZ_LA)
#define OFF_HC1  (OFF_PQ+SZ_PQ)
#define OFF_R1   (OFF_HC1+SZ_HC1)
#define TOTAL_F  (OFF_R1+SZ_R1)

__device__ __align__(256) float g_buf[TOTAL_F];

// ---------------- bf16 transposed split-weight arena: [N][K], hi then lo ----------------
#define W_NI1  0LL
#define W_NI2  65536LL
#define W_EI1  98304LL
#define W_EI2  245760LL
#define W_MSG3 294912LL
#define W_AB   327680LL
#define W_SUM  393216LL
#define W_NU1  425984LL
#define W_NU2  524288LL
#define W_NS1  557056LL
#define W_NS2  565248LL
#define W_ES1  569344LL
#define W_ES2  585728LL
#define W_TOT  589824LL
__device__ __align__(256) __nv_bfloat16 g_wb[2 * W_TOT];

// ---------------- segment descriptor ----------------
struct Seg {
    const float* ptr;
    int ld, div, mul, col0, kend;
};

__device__ __forceinline__ uint32_t s2u(const void* p) {
    uint32_t a;
    asm("{ .reg .u64 t; cvta.to.shared.u64 t, %1; cvt.u32.u64 %0, t; }" : "=r"(a) : "l"(p));
    return a;
}

// =====================================================================
// WMMA tensor GEMM: C = act( concat(seg0,seg1)(row-mapped)[128 x K] @ Wt^T + bias + Cin )
// Wt is [N][K] bf16 split (hi/lo). Block tile 128x64, warps 4x2 of 32x32.
// bf16x3: acc += Ah*Bh + Ah*Bl + Al*Bh  (fp32 accumulate). arelu: relu on A load.
// =====================================================================
#define ALD 72
#define CLD 68
__global__ __launch_bounds__(256) void gemm_wm(
    Seg s0, Seg s1,
    const __nv_bfloat16* __restrict__ Wh, const __nv_bfloat16* __restrict__ Wl, int ldw,
    const float* __restrict__ bias, const float* __restrict__ Cin, int ldcin,
    float* __restrict__ C, int K,
    int relu, int odiv, int omul, int ldc, int pmod, int plim, int arelu)
{
    extern __shared__ char smraw[];
    __nv_bfloat16* Ahs = (__nv_bfloat16*)smraw;          // [128][ALD]
    __nv_bfloat16* Als = Ahs + 128 * ALD;
    __nv_bfloat16* Bhs = Als + 128 * ALD;                // [64][ALD]
    __nv_bfloat16* Bls = Bhs + 64 * ALD;
    float* Cs = (float*)smraw;                           // [128][CLD] (reused)
    int t = threadIdx.x;
    int rowBase = blockIdx.y * 128;
    int n0 = blockIdx.x * 64;
    int wid = t >> 5;
    int wm = wid & 3, wn = wid >> 2;

    wmma::fragment<wmma::accumulator, 16, 16, 16, float> acc[2][2];
#pragma unroll
    for (int i = 0; i < 2; i++)
#pragma unroll
        for (int j = 0; j < 2; j++) wmma::fill_fragment(acc[i][j], 0.f);

    for (int k0 = 0; k0 < K; k0 += 64) {
        const Seg* s = (k0 < s0.kend) ? &s0 : &s1;
        const float* abase = s->ptr + (k0 - s->col0);
        __syncthreads();
        for (int idx = t; idx < 2048; idx += 256) {
            int r = idx >> 4, q = idx & 15;
            int grow = rowBase + r;
            int rr = s->div ? (grow / s->div) * s->mul + (grow % s->div) : grow;
            float4 v = *reinterpret_cast<const float4*>(abase + (size_t)rr * s->ld + q * 4);
            if (arelu) {
                v.x = fmaxf(v.x, 0.f); v.y = fmaxf(v.y, 0.f);
                v.z = fmaxf(v.z, 0.f); v.w = fmaxf(v.w, 0.f);
            }
            __nv_bfloat162 h01 = __floats2bfloat162_rn(v.x, v.y);
            __nv_bfloat162 h23 = __floats2bfloat162_rn(v.z, v.w);
            __nv_bfloat162 l01 = __floats2bfloat162_rn(v.x - __low2float(h01), v.y - __high2float(h01));
            __nv_bfloat162 l23 = __floats2bfloat162_rn(v.z - __low2float(h23), v.w - __high2float(h23));
            uint2 uh, ul;
            uh.x = *reinterpret_cast<uint32_t*>(&h01);
            uh.y = *reinterpret_cast<uint32_t*>(&h23);
            ul.x = *reinterpret_cast<uint32_t*>(&l01);
            ul.y = *reinterpret_cast<uint32_t*>(&l23);
            *reinterpret_cast<uint2*>(Ahs + r * ALD + q * 4) = uh;
            *reinterpret_cast<uint2*>(Als + r * ALD + q * 4) = ul;
        }
        for (int idx = t; idx < 512; idx += 256) {
            int n = idx >> 3, cc = idx & 7;
            size_t so = (size_t)(n0 + n) * ldw + k0 + cc * 8;
            *reinterpret_cast<uint4*>(Bhs + n * ALD + cc * 8) =
                *reinterpret_cast<const uint4*>(Wh + so);
            *reinterpret_cast<uint4*>(Bls + n * ALD + cc * 8) =
                *reinterpret_cast<const uint4*>(Wl + so);
        }
        __syncthreads();
#pragma unroll
        for (int kk = 0; kk < 4; kk++) {
            wmma::fragment<wmma::matrix_a, 16, 16, 16, __nv_bfloat16, wmma::row_major> fah[2], fal[2];
#pragma unroll
            for (int mf = 0; mf < 2; mf++) {
                wmma::load_matrix_sync(fah[mf], Ahs + (wm * 32 + mf * 16) * ALD + kk * 16, ALD);
                wmma::load_matrix_sync(fal[mf], Als + (wm * 32 + mf * 16) * ALD + kk * 16, ALD);
            }
#pragma unroll
            for (int nf = 0; nf < 2; nf++) {
                wmma::fragment<wmma::matrix_b, 16, 16, 16, __nv_bfloat16, wmma::col_major> fbh, fbl;
                wmma::load_matrix_sync(fbh, Bhs + (wn * 32 + nf * 16) * ALD + kk * 16, ALD);
                wmma::load_matrix_sync(fbl, Bls + (wn * 32 + nf * 16) * ALD + kk * 16, ALD);
#pragma unroll
                for (int mf = 0; mf < 2; mf++) {
                    wmma::mma_sync(acc[mf][nf], fah[mf], fbh, acc[mf][nf]);
                    wmma::mma_sync(acc[mf][nf], fah[mf], fbl, acc[mf][nf]);
                    wmma::mma_sync(acc[mf][nf], fal[mf], fbh, acc[mf][nf]);
                }
            }
        }
    }
    __syncthreads();
#pragma unroll
    for (int mf = 0; mf < 2; mf++)
#pragma unroll
        for (int nf = 0; nf < 2; nf++)
            wmma::store_matrix_sync(Cs + (wm * 32 + mf * 16) * CLD + wn * 32 + nf * 16,
                                    acc[mf][nf], CLD, wmma::mem_row_major);
    __syncthreads();
    for (int idx = t; idx < 2048; idx += 256) {
        int r = idx >> 4, c4 = (idx & 15) * 4;
        float4 v = *reinterpret_cast<const float4*>(Cs + r * CLD + c4);
        int grow = rowBase + r;
        int col = n0 + c4;
        if (bias) {
            float4 bb = *reinterpret_cast<const float4*>(bias + col);
            v.x += bb.x; v.y += bb.y; v.z += bb.z; v.w += bb.w;
        }
        if (Cin) {
            float4 cc = *reinterpret_cast<const float4*>(Cin + (size_t)grow * ldcin + col);
            v.x += cc.x; v.y += cc.y; v.z += cc.z; v.w += cc.w;
        }
        if (relu) {
            v.x = fmaxf(v.x, 0.f); v.y = fmaxf(v.y, 0.f);
            v.z = fmaxf(v.z, 0.f); v.w = fmaxf(v.w, 0.f);
        }
        if (pmod != 0 && (grow % pmod) >= plim) { v.x = v.y = v.z = v.w = 0.f; }
        int orow = odiv ? (grow / odiv) * omul + (grow % odiv) : grow;
        *reinterpret_cast<float4*>(C + (size_t)orow * ldc + col) = v;
    }
}
#define WM_SMEM ((2 * 128 * ALD + 2 * 64 * ALD) * 2)

// =====================================================================
// WMMA batched GEMM (plan GEMMs): C = alpha * op(A) @ op(B), bf16x3 split.
// =====================================================================
__global__ __launch_bounds__(256) void gemm_bw(
    const float* __restrict__ A, long long Abs, int lda, int aT,
    const float* __restrict__ B, long long Bbs, int ldb, int bT,
    float* __restrict__ C, long long Cbs, int ldc,
    int K, float alpha)
{
    __shared__ __align__(16) char sm[4 * 64 * ALD * 2];
    __nv_bfloat16* Ah = (__nv_bfloat16*)sm;
    __nv_bfloat16* Al = Ah + 64 * ALD;
    __nv_bfloat16* Bh = Al + 64 * ALD;
    __nv_bfloat16* Bl = Bh + 64 * ALD;
    float* Cs = (float*)sm;
    const float* Ab = A + (size_t)blockIdx.z * Abs;
    const float* Bb = B + (size_t)blockIdx.z * Bbs;
    int t = threadIdx.x;
    int m0 = blockIdx.y * 64, n0 = blockIdx.x * 64;
    int wid = t >> 5, wm = wid & 3, wn = wid >> 2;

    wmma::fragment<wmma::accumulator, 16, 16, 16, float> acc[2];
    wmma::fill_fragment(acc[0], 0.f);
    wmma::fill_fragment(acc[1], 0.f);

    for (int k0 = 0; k0 < K; k0 += 64) {
        __syncthreads();
        if (!aT) {
            for (int idx = t; idx < 1024; idx += 256) {
                int r = idx >> 4, q = idx & 15;
                float4 v = *reinterpret_cast<const float4*>(Ab + (size_t)(m0 + r) * lda + k0 + q * 4);
                __nv_bfloat162 h01 = __floats2bfloat162_rn(v.x, v.y);
                __nv_bfloat162 h23 = __floats2bfloat162_rn(v.z, v.w);
                __nv_bfloat162 l01 = __floats2bfloat162_rn(v.x - __low2float(h01), v.y - __high2float(h01));
                __nv_bfloat162 l23 = __floats2bfloat162_rn(v.z - __low2float(h23), v.w - __high2float(h23));
                uint2 uh, ul;
                uh.x = *reinterpret_cast<uint32_t*>(&h01);
                uh.y = *reinterpret_cast<uint32_t*>(&h23);
                ul.x = *reinterpret_cast<uint32_t*>(&l01);
                ul.y = *reinterpret_cast<uint32_t*>(&l23);
                *reinterpret_cast<uint2*>(Ah + r * ALD + q * 4) = uh;
                *reinterpret_cast<uint2*>(Al + r * ALD + q * 4) = ul;
            }
        } else {
            for (int idx = t; idx < 1024; idx += 256) {
                int kk = idx >> 4, r4 = (idx & 15) * 4;
                float4 v = *reinterpret_cast<const float4*>(Ab + (size_t)(k0 + kk) * lda + m0 + r4);
                float vv[4] = {v.x, v.y, v.z, v.w};
#pragma unroll
                for (int j = 0; j < 4; j++) {
                    __nv_bfloat16 h = __float2bfloat16(vv[j]);
                    Ah[(r4 + j) * ALD + kk] = h;
                    Al[(r4 + j) * ALD + kk] = __float2bfloat16(vv[j] - __bfloat162float(h));
                }
            }
        }
        if (bT) {
            for (int idx = t; idx < 1024; idx += 256) {
                int n = idx >> 4, q = idx & 15;
                float4 v = *reinterpret_cast<const float4*>(Bb + (size_t)(n0 + n) * ldb + k0 + q * 4);
                __nv_bfloat162 h01 = __floats2bfloat162_rn(v.x, v.y);
                __nv_bfloat162 h23 = __floats2bfloat162_rn(v.z, v.w);
                __nv_bfloat162 l01 = __floats2bfloat162_rn(v.x - __low2float(h01), v.y - __high2float(h01));
                __nv_bfloat162 l23 = __floats2bfloat162_rn(v.z - __low2float(h23), v.w - __high2float(h23));
                uint2 uh, ul;
                uh.x = *reinterpret_cast<uint32_t*>(&h01);
                uh.y = *reinterpret_cast<uint32_t*>(&h23);
                ul.x = *reinterpret_cast<uint32_t*>(&l01);
                ul.y = *reinterpret_cast<uint32_t*>(&l23);
                *reinterpret_cast<uint2*>(Bh + n * ALD + q * 4) = uh;
                *reinterpret_cast<uint2*>(Bl + n * ALD + q * 4) = ul;
            }
        } else {
            for (int idx = t; idx < 1024; idx += 256) {
                int kk = idx >> 4, n4 = (idx & 15) * 4;
                float4 v = *reinterpret_cast<const float4*>(Bb + (size_t)(k0 + kk) * ldb + n0 + n4);
                float vv[4] = {v.x, v.y, v.z, v.w};
#pragma unroll
                for (int j = 0; j < 4; j++) {
                    __nv_bfloat16 h = __float2bfloat16(vv[j]);
                    Bh[(n4 + j) * ALD + kk] = h;
                    Bl[(n4 + j) * ALD + kk] = __float2bfloat16(vv[j] - __bfloat162float(h));
                }
            }
        }
        __syncthreads();
#pragma unroll
        for (int kk = 0; kk < 4; kk++) {
            wmma::fragment<wmma::matrix_a, 16, 16, 16, __nv_bfloat16, wmma::row_major> fah, fal;
            wmma::load_matrix_sync(fah, Ah + (wm * 16) * ALD + kk * 16, ALD);
            wmma::load_matrix_sync(fal, Al + (wm * 16) * ALD + kk * 16, ALD);
#pragma unroll
            for (int nf = 0; nf < 2; nf++) {
                wmma::fragment<wmma::matrix_b, 16, 16, 16, __nv_bfloat16, wmma::col_major> fbh, fbl;
                wmma::load_matrix_sync(fbh, Bh + (wn * 32 + nf * 16) * ALD + kk * 16, ALD);
                wmma::load_matrix_sync(fbl, Bl + (wn * 32 + nf * 16) * ALD + kk * 16, ALD);
                wmma::mma_sync(acc[nf], fah, fbh, acc[nf]);
                wmma::mma_sync(acc[nf], fah, fbl, acc[nf]);
                wmma::mma_sync(acc[nf], fal, fbh, acc[nf]);
            }
        }
    }
    __syncthreads();
#pragma unroll
    for (int nf = 0; nf < 2; nf++)
        wmma::store_matrix_sync(Cs + (wm * 16) * CLD + wn * 32 + nf * 16,
                                acc[nf], CLD, wmma::mem_row_major);
    __syncthreads();
    float* Cb = C + (size_t)blockIdx.z * Cbs;
    for (int idx = t; idx < 1024; idx += 256) {
        int r = idx >> 4, c4 = (idx & 15) * 4;
        float4 v = *reinterpret_cast<const float4*>(Cs + r * CLD + c4);
        v.x *= alpha; v.y *= alpha; v.z *= alpha; v.w *= alpha;
        *reinterpret_cast<float4*>(Cb + (size_t)(m0 + r) * ldc + n0 + c4) = v;
    }
}

// =====================================================================
// SIMT fused GEMM (one-time prep only)
// =====================================================================
template<int BM>
__global__ __launch_bounds__(256) void gemm_seg(
    Seg s0, Seg s1,
    const float* __restrict__ W, const float* __restrict__ bias,
    float* __restrict__ C, int M, int N, int K, int ldc)
{
    const int RI = BM / 16;
    __shared__ float As[8][BM];
    __shared__ float Bs[8][128];
    int t = threadIdx.x;
    int rowBase = blockIdx.y * BM;
    int nBase   = blockIdx.x * 128;
    int tx = t & 15, ty = t >> 4;

    float acc[RI][8];
#pragma unroll
    for (int i = 0; i < RI; i++)
#pragma unroll
        for (int j = 0; j < 8; j++) acc[i][j] = 0.f;

    for (int k0 = 0; k0 < K; k0 += 8) {
        if (BM == 128 || t < 128) {
            int ar = t >> 1;
            int ak = (t & 1) * 4;
            int grow = rowBase + ar;
            float4 av = make_float4(0.f, 0.f, 0.f, 0.f);
            int gk = k0 + ak;
            const Seg* s = (gk < s0.kend) ? &s0 : &s1;
            if (grow < M && s->ptr) {
                int rr = s->div ? (grow / s->div) * s->mul + (grow % s->div) : grow;
                av = *reinterpret_cast<const float4*>(s->ptr + (size_t)rr * s->ld + (gk - s->col0));
            }
            As[ak + 0][ar] = av.x; As[ak + 1][ar] = av.y;
            As[ak + 2][ar] = av.z; As[ak + 3][ar] = av.w;
        }
        {
            int bk = t >> 5, bn = (t & 31) * 4;
            float4 bv = make_float4(0.f, 0.f, 0.f, 0.f);
            int gn = nBase + bn;
            if (gn < N) bv = *reinterpret_cast<const float4*>(W + (size_t)(k0 + bk) * N + gn);
            *reinterpret_cast<float4*>(&Bs[bk][bn]) = bv;
        }
        __syncthreads();
#pragma unroll
        for (int kk = 0; kk < 8; kk++) {
            float a[RI];
            {
                float4 a0 = *reinterpret_cast<const float4*>(&As[kk][ty * 4]);
                a[0] = a0.x; a[1] = a0.y; a[2] = a0.z; a[3] = a0.w;
                if (BM == 128) {
                    float4 a1 = *reinterpret_cast<const float4*>(&As[kk][64 + ty * 4]);
                    a[4] = a1.x; a[5] = a1.y; a[6] = a1.z; a[7] = a1.w;
                }
            }
            float4 b0 = *reinterpret_cast<const float4*>(&Bs[kk][tx * 4]);
            float4 b1 = *reinterpret_cast<const float4*>(&Bs[kk][64 + tx * 4]);
            float b[8] = {b0.x, b0.y, b0.z, b0.w, b1.x, b1.y, b1.z, b1.w};
#pragma unroll
            for (int i = 0; i < RI; i++)
#pragma unroll
                for (int j = 0; j < 8; j++) acc[i][j] += a[i] * b[j];
        }
        __syncthreads();
    }
#pragma unroll
    for (int i = 0; i < RI; i++) {
        int r;
        if (BM == 128) r = rowBase + ((i < 4) ? (ty * 4 + i) : (64 + ty * 4 + i - 4));
        else           r = rowBase + ty * 4 + i;
        if (r >= M) continue;
        float* crow = C + (size_t)r * ldc;
#pragma unroll
        for (int jj = 0; jj < 2; jj++) {
            int col = nBase + ((jj == 0) ? tx * 4 : 64 + tx * 4);
            if (col >= N) continue;
            float v0 = acc[i][jj * 4 + 0], v1 = acc[i][jj * 4 + 1];
            float v2 = acc[i][jj * 4 + 2], v3 = acc[i][jj * 4 + 3];
            if (bias) {
                float4 bb = *reinterpret_cast<const float4*>(bias + col);
                v0 += bb.x; v1 += bb.y; v2 += bb.z; v3 += bb.w;
            }
            float4 vv; vv.x = v0; vv.y = v1; vv.z = v2; vv.w = v3;
            *reinterpret_cast<float4*>(crow + col) = vv;
        }
    }
}

// =====================================================================
// SIMT batched GEMM (logit GEMMs only — fp32 for Sinkhorn input precision)
// =====================================================================
__global__ __launch_bounds__(256) void gemm_bat(
    const float* __restrict__ A, long long Abs, int lda, int aT,
    const float* __restrict__ B, long long Bbs, int ldb, int bT,
    float* __restrict__ C, long long Cbs, int ldc,
    int M, int N, int K, float alpha)
{
    __shared__ float As[16][128];
    __shared__ float Bs[16][128];
    int t = threadIdx.x;
    int b = blockIdx.z;
    int m0 = blockIdx.y * 128;
    int n0 = blockIdx.x * 128;
    const float* Ab = A + (size_t)b * Abs;
    const float* Bb = B + (size_t)b * Bbs;
    int tx = t & 15, ty = t >> 4;
    float acc[8][8];
#pragma unroll
    for (int i = 0; i < 8; i++)
#pragma unroll
        for (int j = 0; j < 8; j++) acc[i][j] = 0.f;

    for (int k0 = 0; k0 < K; k0 += 16) {
        if (!aT) {
            int r = t >> 1, k4 = (t & 1) * 8;
            float4 v0 = make_float4(0.f,0.f,0.f,0.f), v1 = v0;
            if (m0 + r < M) {
                v0 = *reinterpret_cast<const float4*>(Ab + (size_t)(m0 + r) * lda + k0 + k4);
                v1 = *reinterpret_cast<const float4*>(Ab + (size_t)(m0 + r) * lda + k0 + k4 + 4);
            }
            As[k4+0][r]=v0.x; As[k4+1][r]=v0.y; As[k4+2][r]=v0.z; As[k4+3][r]=v0.w;
            As[k4+4][r]=v1.x; As[k4+5][r]=v1.y; As[k4+6][r]=v1.z; As[k4+7][r]=v1.w;
        } else {
            int kk = t >> 4, r4 = (t & 15) * 8;
            float4 v0 = *reinterpret_cast<const float4*>(Ab + (size_t)(k0 + kk) * lda + m0 + r4);
            float4 v1 = *reinterpret_cast<const float4*>(Ab + (size_t)(k0 + kk) * lda + m0 + r4 + 4);
            *reinterpret_cast<float4*>(&As[kk][r4])     = v0;
            *reinterpret_cast<float4*>(&As[kk][r4 + 4]) = v1;
        }
        if (!bT) {
            int kk = t >> 4, n4 = (t & 15) * 8;
            float4 v0 = make_float4(0.f,0.f,0.f,0.f), v1 = v0;
            if (n0 + n4 < N) {
                v0 = *reinterpret_cast<const float4*>(Bb + (size_t)(k0 + kk) * ldb + n0 + n4);
                v1 = *reinterpret_cast<const float4*>(Bb + (size_t)(k0 + kk) * ldb + n0 + n4 + 4);
            }
            *reinterpret_cast<float4*>(&Bs[kk][n4])     = v0;
            *reinterpret_cast<float4*>(&Bs[kk][n4 + 4]) = v1;
        } else {
            int n = t >> 1, k4 = (t & 1) * 8;
            float4 v0 = make_float4(0.f,0.f,0.f,0.f), v1 = v0;
            if (n0 + n < N) {
                v0 = *reinterpret_cast<const float4*>(Bb + (size_t)(n0 + n) * ldb + k0 + k4);
                v1 = *reinterpret_cast<const float4*>(Bb + (size_t)(n0 + n) * ldb + k0 + k4 + 4);
            }
            Bs[k4+0][n]=v0.x; Bs[k4+1][n]=v0.y; Bs[k4+2][n]=v0.z; Bs[k4+3][n]=v0.w;
            Bs[k4+4][n]=v1.x; Bs[k4+5][n]=v1.y; Bs[k4+6][n]=v1.z; Bs[k4+7][n]=v1.w;
        }
        __syncthreads();
#pragma unroll
        for (int kk = 0; kk < 16; kk++) {
            float4 a0 = *reinterpret_cast<const float4*>(&As[kk][ty * 4]);
            float4 a1 = *reinterpret_cast<const float4*>(&As[kk][64 + ty * 4]);
            float4 b0 = *reinterpret_cast<const float4*>(&Bs[kk][tx * 4]);
            float4 b1 = *reinterpret_cast<const float4*>(&Bs[kk][64 + tx * 4]);
            float a[8] = {a0.x,a0.y,a0.z,a0.w,a1.x,a1.y,a1.z,a1.w};
            float bb[8] = {b0.x,b0.y,b0.z,b0.w,b1.x,b1.y,b1.z,b1.w};
#pragma unroll
            for (int i = 0; i < 8; i++)
#pragma unroll
                for (int j = 0; j < 8; j++) acc[i][j] += a[i] * bb[j];
        }
        __syncthreads();
    }
    float* Cb = C + (size_t)b * Cbs;
#pragma unroll
    for (int i = 0; i < 8; i++) {
        int row = (i < 4) ? (ty * 4 + i) : (64 + ty * 4 + i - 4);
        if (m0 + row >= M) continue;
#pragma unroll
        for (int jj = 0; jj < 2; jj++) {
            int col = (jj == 0) ? tx * 4 : 64 + tx * 4;
            if (n0 + col >= N) continue;
            float4 vv;
            vv.x = alpha * acc[i][jj*4+0]; vv.y = alpha * acc[i][jj*4+1];
            vv.z = alpha * acc[i][jj*4+2]; vv.w = alpha * acc[i][jj*4+3];
            *reinterpret_cast<float4*>(Cb + (size_t)(m0 + row) * ldc + n0 + col) = vv;
        }
    }
}

// ---------------- weight prep: transpose + bf16 hi/lo split ----------------
__global__ void tsplit(const float* __restrict__ W, int K, int N,
                       __nv_bfloat16* __restrict__ Dh, __nv_bfloat16* __restrict__ Dl) {
    int gid = blockIdx.x * 256 + threadIdx.x;
    if (gid >= K * N) return;
    int k = gid / N, n = gid % N;
    float v = W[gid];
    __nv_bfloat16 h = __float2bfloat16(v);
    Dh[(size_t)n * K + k] = h;
    Dl[(size_t)n * K + k] = __float2bfloat16(v - __bfloat162float(h));
}
__global__ void tssum(const float* __restrict__ msgW,
                      __nv_bfloat16* __restrict__ Dh, __nv_bfloat16* __restrict__ Dl) {
    int gid = blockIdx.x * 256 + threadIdx.x;
    int k = gid >> 8, n = gid & 255;
    float v = msgW[k * 256 + n] + msgW[(128 + k) * 256 + n];
    __nv_bfloat16 h = __float2bfloat16(v);
    Dh[(size_t)n * 128 + k] = h;
    Dl[(size_t)n * 128 + k] = __float2bfloat16(v - __bfloat162float(h));
}

// ---------------- elementwise / scatter ----------------
__device__ __forceinline__ void red_add_v4(float* addr, float4 v) {
    asm volatile("red.global.add.v4.f32 [%0], {%1,%2,%3,%4};"
                 :: "l"(addr), "f"(v.x), "f"(v.y), "f"(v.z), "f"(v.w) : "memory");
}
__global__ void zero_k(float* __restrict__ p, long long n4) {
    long long i = (long long)blockIdx.x * blockDim.x + threadIdx.x;
    long long stride = (long long)gridDim.x * blockDim.x;
    for (; i < n4; i += stride)
        reinterpret_cast<float4*>(p)[i] = make_float4(0.f, 0.f, 0.f, 0.f);
}
__global__ void scatter_agg(const float* __restrict__ XW, const float* __restrict__ R,
                            const int* __restrict__ fi, const int* __restrict__ ti,
                            float* __restrict__ agg) {
    int gid = blockIdx.x * 256 + threadIdx.x;
    int e = gid >> 6, c = (gid & 63) * 4;
    int f = fi[e], t = ti[e];
    float4 x1f = *reinterpret_cast<const float4*>(XW + (size_t)f * 512 + c);
    float4 x2f = *reinterpret_cast<const float4*>(XW + (size_t)f * 512 + 256 + c);
    float4 x1t = *reinterpret_cast<const float4*>(XW + (size_t)t * 512 + c);
    float4 x2t = *reinterpret_cast<const float4*>(XW + (size_t)t * 512 + 256 + c);
    float4 r   = *reinterpret_cast<const float4*>(R + (size_t)e * 256 + c);
    float4 fwd; fwd.x = x1f.x + x2t.x + r.x; fwd.y = x1f.y + x2t.y + r.y;
                fwd.z = x1f.z + x2t.z + r.z; fwd.w = x1f.w + x2t.w + r.w;
    float4 bwd; bwd.x = x1t.x + x2f.x + r.x; bwd.y = x1t.y + x2f.y + r.y;
                bwd.z = x1t.z + x2f.z + r.z; bwd.w = x1t.w + x2f.w + r.w;
    red_add_v4(agg + (size_t)t * 256 + c, fwd);
    red_add_v4(agg + (size_t)f * 256 + c, bwd);
}
// msgs + fused zeroing of agg for the NEXT scatter step.
// agg holds VN*256 floats = VN*64 float4s; guard the zero store.
__global__ void msgs_k(const float* __restrict__ Y, const float* __restrict__ R,
                       const int* __restrict__ fi, const int* __restrict__ ti,
                       float* __restrict__ upEp, float* __restrict__ agg) {
    int gid = blockIdx.x * 256 + threadIdx.x;
    int e = gid >> 6, c = (gid & 63) * 4;
    int f = fi[e], t = ti[e];
    float4 yf = *reinterpret_cast<const float4*>(Y + (size_t)f * 256 + c);
    float4 yt = *reinterpret_cast<const float4*>(Y + (size_t)t * 256 + c);
    float4 r  = *reinterpret_cast<const float4*>(R + (size_t)e * 256 + c);
    float4 v;
    v.x = yf.x + yt.x + 2.f * r.x; v.y = yf.y + yt.y + 2.f * r.y;
    v.z = yf.z + yt.z + 2.f * r.z; v.w = yf.w + yt.w + 2.f * r.w;
    int row = (e / 192) * 256 + (e % 192);
    *reinterpret_cast<float4*>(upEp + (size_t)row * 1536 + c) = v;
    if (gid < VN * 64)
        reinterpret_cast<float4*>(agg)[gid] = make_float4(0.f, 0.f, 0.f, 0.f);
}

// ---------------- Sinkhorn (probability domain) ----------------
__global__ __launch_bounds__(256) void sink_node(float* __restrict__ la) {
    __shared__ float tile[64][65];
    __shared__ float cinv[64];
    int b = blockIdx.x, t = threadIdx.x;
    const size_t base = (size_t)b * 4096;
    for (int idx = t; idx < 4096; idx += 256)
        tile[idx >> 6][idx & 63] = la[base + idx];
    __syncthreads();
    int w = t >> 5, l = t & 31;
    for (int it = 0; it < 10; it++) {
#pragma unroll
        for (int i = 0; i < 8; i++) {
            int r = w * 8 + i;
            float v0 = tile[r][l], v1 = tile[r][l + 32];
            if (it == 0) {
                float m = fmaxf(v0, v1);
                for (int o = 16; o; o >>= 1) m = fmaxf(m, __shfl_xor_sync(0xffffffffu, m, o));
                v0 = expf(v0 - m); v1 = expf(v1 - m);
            }
            float s = v0 + v1;
            for (int o = 16; o; o >>= 1) s += __shfl_xor_sync(0xffffffffu, s, o);
            float inv = 1.f / s;
            tile[r][l] = v0 * inv; tile[r][l + 32] = v1 * inv;
        }
        __syncthreads();
        if (t < 64) {
            float s = 0.f;
            for (int q = 0; q < 64; q++) s += tile[q][t];
            cinv[t] = 1.f / s;
        }
        __syncthreads();
        for (int idx = t; idx < 4096; idx += 256) {
            int r = idx >> 6, c = idx & 63;
            tile[r][c] *= cinv[c];
        }
        __syncthreads();
    }
    for (int idx = t; idx < 4096; idx += 256)
        la[base + idx] = tile[idx >> 6][idx & 63];
}

// edge: 2-CTA cluster per batch; tile resident in smem for all 10 iters.
__global__ __launch_bounds__(256) __cluster_dims__(2, 1, 1)
void sink_edge(float* __restrict__ la) {
    extern __shared__ float sm[];
    float* tile = sm;                         // [128][256]
    float* ps   = sm + 32768;                 // [2][256]
    int t = threadIdx.x;
    uint32_t rank;
    asm("mov.u32 %0, %%cluster_ctarank;" : "=r"(rank));
    float* g = la + (size_t)(blockIdx.x >> 1) * 65536 + (size_t)rank * 32768;
    for (int idx = t * 4; idx < 32768; idx += 1024)
        *reinterpret_cast<float4*>(tile + idx) = *reinterpret_cast<const float4*>(g + idx);
    __syncthreads();
    int w = t >> 5, l = t & 31;
    for (int it = 0; it < 10; it++) {
#pragma unroll 1
        for (int i = 0; i < 16; i++) {
            int r = w * 16 + i;
            float v[8];
#pragma unroll
            for (int j = 0; j < 8; j++) v[j] = tile[r * 256 + l + 32 * j];
            if (it == 0) {
                float m = v[0];
#pragma unroll
                for (int j = 1; j < 8; j++) m = fmaxf(m, v[j]);
                for (int o = 16; o; o >>= 1) m = fmaxf(m, __shfl_xor_sync(0xffffffffu, m, o));
#pragma unroll
                for (int j = 0; j < 8; j++) v[j] = expf(v[j] - m);
            }
            float s = 0.f;
#pragma unroll
            for (int j = 0; j < 8; j++) s += v[j];
            for (int o = 16; o; o >>= 1) s += __shfl_xor_sync(0xffffffffu, s, o);
            float inv = 1.f / s;
#pragma unroll
            for (int j = 0; j < 8; j++) tile[r * 256 + l + 32 * j] = v[j] * inv;
        }
        __syncthreads();
        float cs = 0.f;
#pragma unroll 8
        for (int r = 0; r < 128; r++) cs += tile[r * 256 + t];
        int par = it & 1;
        ps[par * 256 + t] = cs;
        __syncthreads();
        asm volatile("barrier.cluster.arrive.aligned;" ::: "memory");
        asm volatile("barrier.cluster.wait.aligned;" ::: "memory");
        uint32_t myaddr = s2u(&ps[par * 256 + t]);
        uint32_t paddr;
        asm("mapa.shared::cluster.u32 %0, %1, %2;" : "=r"(paddr) : "r"(myaddr), "r"(rank ^ 1u));
        float pv;
        asm volatile("ld.shared::cluster.f32 %0, [%1];" : "=f"(pv) : "r"(paddr));
        float inv = 1.f / (cs + pv);
#pragma unroll 8
        for (int r = 0; r < 128; r++) tile[r * 256 + t] *= inv;
        __syncthreads();
    }
    for (int idx = t * 4; idx < 32768; idx += 1024)
        *reinterpret_cast<float4*>(g + idx) = *reinterpret_cast<const float4*>(tile + idx);
    asm volatile("barrier.cluster.arrive.aligned;" ::: "memory");
    asm volatile("barrier.cluster.wait.aligned;" ::: "memory");
}
#define SE_SMEM ((32768 + 512) * 4)

__global__ void score_k(const float* __restrict__ upN, const float* __restrict__ pq,
                        float* __restrict__ out) {
    __shared__ float sh[256];
    int b = blockIdx.x;
    float s = 0.f;
    for (int idx = threadIdx.x; idx < 64 * 128; idx += 256) {
        int q = idx >> 7, d = idx & 127;
        float fqv = upN[(size_t)((2 * b) * 64 + q) * 768 + 640 + d];
        float v = fqv - pq[(size_t)(b * 64 + q) * 128 + d];
        s += fmaxf(v, 0.f);
    }
    sh[threadIdx.x] = s;
    __syncthreads();
    for (int o = 128; o; o >>= 1) {
        if (threadIdx.x < o) sh[threadIdx.x] += sh[threadIdx.x + o];
        __syncthreads();
    }
    if (threadIdx.x == 0) out[b] = -sh[0];
}

// ---------------- host helpers ----------------
static inline Seg mkseg(const float* p, int ld, int div, int mul, int col0, int kend) {
    Seg s; s.ptr = p; s.ld = ld; s.div = div; s.mul = mul; s.col0 = col0; s.kend = kend;
    return s;
}
static inline Seg segz() { return mkseg(nullptr, 4, 0, 0, 0, 1 << 30); }

static inline void lwm(Seg a, Seg b, const __nv_bfloat16* wb, long long woff, int ldw,
                       const float* bias, const float* Cin, int ldcin,
                       float* C, int M, int N, int K, int relu,
                       int odiv, int omul, int ldc, int pmod, int plim, int arelu = 0) {
    dim3 g(N / 64, M / 128);
    gemm_wm<<<g, 256, WM_SMEM>>>(a, b, wb + woff, wb + W_TOT + woff, ldw,
                                 bias, Cin, ldcin, C, K, relu, odiv, omul, ldc,
                                 pmod, plim, arelu);
}
static inline void lbat(const float* A, long long Abs, int lda, int aT,
                        const float* B, long long Bbs, int ldb, int bT,
                        float* C, long long Cbs, int ldc,
                        int M, int N, int K, float alpha, int batch) {
    dim3 g((N + 127) / 128, (M + 127) / 128, batch);
    gemm_bat<<<g, 256>>>(A, Abs, lda, aT, B, Bbs, ldb, bT, C, Cbs, ldc, M, N, K, alpha);
}
static inline void lbw(const float* A, long long Abs, int lda, int aT,
                       const float* B, long long Bbs, int ldb, int bT,
                       float* C, long long Cbs, int ldc,
                       int M, int N, int K, float alpha, int batch) {
    dim3 g(N / 64, M / 64, batch);
    gemm_bw<<<g, 256>>>(A, Abs, lda, aT, B, Bbs, ldb, bT, C, Cbs, ldc, K, alpha);
}

extern "C" void kernel_launch(void* const* d_in, const int* in_sizes, int n_in,
                              void* d_out, int out_size) {
    const float* nodef = (const float*)d_in[0];
    const float* edgef = (const float*)d_in[1];
    const int*   fromi = (const int*)d_in[2];
    const int*   toi   = (const int*)d_in[3];
    const float* encnW = (const float*)d_in[4];
    const float* encnB = (const float*)d_in[5];
    const float* enceW = (const float*)d_in[6];
    const float* enceB = (const float*)d_in[7];
    const float* niW1  = (const float*)d_in[8];
    const float* niB1  = (const float*)d_in[9];
    const float* niW2  = (const float*)d_in[10];
    const float* niB2  = (const float*)d_in[11];
    const float* eiW1  = (const float*)d_in[12];
    const float* eiB1  = (const float*)d_in[13];
    const float* eiW2  = (const float*)d_in[14];
    const float* eiB2  = (const float*)d_in[15];
    const float* msgW  = (const float*)d_in[16];
    const float* msgB  = (const float*)d_in[17];
    const float* nuW1  = (const float*)d_in[18];
    const float* nuB1  = (const float*)d_in[19];
    const float* nuW2  = (const float*)d_in[20];
    const float* nuB2  = (const float*)d_in[21];
    const float* nsW1  = (const float*)d_in[22];
    const float* nsB1  = (const float*)d_in[23];
    const float* nsW2  = (const float*)d_in[24];
    const float* nsB2  = (const float*)d_in[25];
    const float* esW1  = (const float*)d_in[26];
    const float* esB1  = (const float*)d_in[27];
    const float* esW2  = (const float*)d_in[28];
    const float* esB2  = (const float*)d_in[29];
    float* out = (float*)d_out;

    float* base;
    cudaGetSymbolAddress((void**)&base, g_buf);
    __nv_bfloat16* wb;
    cudaGetSymbolAddress((void**)&wb, g_wb);
    float* upN  = base + OFF_UPN;
    float* upE  = base + OFF_UPE;
    float* stN  = base + OFF_STN;
    float* stE  = base + OFF_STE;
    float* encN = base + OFF_ENCN;
    float* encE = base + OFF_ENCE;
    float* preN = base + OFF_PREN;
    float* preE = base + OFF_PREE;
    float* hidn = base + OFF_HIDN;
    float* hcmb = base + OFF_HCMB;
    float* hide = base + OFF_HIDE;
    float* ecmb = base + OFF_ECMB;
    float* XW   = base + OFF_XW;
    float* R    = base + OFF_R;
    float* agg  = base + OFF_AGG;
    float* hidu = base + OFF_HIDU;
    float* Y    = base + OFF_Y;
    float* tmp  = base + OFF_TMP;
    float* tqc  = base + OFF_TQC;
    float* la   = base + OFF_LA;
    float* pq   = base + OFF_PQ;
    float* hcmb1 = base + OFF_HC1;
    float* R1    = base + OFF_R1;

    cudaFuncSetAttribute(gemm_wm, cudaFuncAttributeMaxDynamicSharedMemorySize, WM_SMEM);
    cudaFuncSetAttribute(sink_edge, cudaFuncAttributeMaxDynamicSharedMemorySize, SE_SMEM);

    // ---- weight prep (transpose + bf16 split) ----
    tsplit<<<256, 256>>>(niW1, 256, 256, wb + W_NI1, wb + W_TOT + W_NI1);
    tsplit<<<128, 256>>>(niW2, 256, 128, wb + W_NI2, wb + W_TOT + W_NI2);
    tsplit<<<576, 256>>>(eiW1, 384, 384, wb + W_EI1, wb + W_TOT + W_EI1);
    tsplit<<<192, 256>>>(eiW2, 384, 128, wb + W_EI2, wb + W_TOT + W_EI2);
    tsplit<<<128, 256>>>(msgW + 256 * 256, 128, 256, wb + W_MSG3, wb + W_TOT + W_MSG3);
    tsplit<<<128, 256>>>(msgW, 128, 256, wb + W_AB, wb + W_TOT + W_AB);
    tsplit<<<128, 256>>>(msgW + 128 * 256, 128, 256, wb + W_AB + 32768, wb + W_TOT + W_AB + 32768);
    tssum<<<128, 256>>>(msgW, wb + W_SUM, wb + W_TOT + W_SUM);
    tsplit<<<384, 256>>>(nuW1, 384, 256, wb + W_NU1, wb + W_TOT + W_NU1);
    tsplit<<<128, 256>>>(nuW2, 256, 128, wb + W_NU2, wb + W_TOT + W_NU2);
    tsplit<<<32, 256>>>(nsW1, 128, 64, wb + W_NS1, wb + W_TOT + W_NS1);
    tsplit<<<16, 256>>>(nsW2, 64, 64, wb + W_NS2, wb + W_TOT + W_NS2);
    tsplit<<<64, 256>>>(esW1, 256, 64, wb + W_ES1, wb + W_TOT + W_ES1);
    tsplit<<<16, 256>>>(esW2, 64, 64, wb + W_ES2, wb + W_TOT + W_ES2);

    // ---- one-time SIMT prep GEMMs ----
    {
        dim3 g1(1, VN / 64);
        gemm_seg<64><<<g1, 256>>>(mkseg(nodef, 32, 0, 0, 0, 32), segz(), encnW, encnB, encN, VN, 128, 32, 128);
        dim3 g2(1, VE / 64);
        gemm_seg<64><<<g2, 256>>>(mkseg(edgef, 32, 0, 0, 0, 32), segz(), enceW, enceB, encE, VE, 128, 32, 128);
        dim3 g3(2, VN / 64);
        gemm_seg<64><<<g3, 256>>>(mkseg(encN, 128, 0, 0, 0, 128), segz(), niW1, niB1, preN, VN, 256, 128, 256);
        dim3 g4(3, VE / 64);
        gemm_seg<64><<<g4, 256>>>(mkseg(encE, 128, 0, 0, 0, 128), segz(), eiW1, eiB1, preE, VE, 384, 128, 384);
    }

    // ---- k-invariant precomputes: hcmb1, R1, and the ENTIRE p==1 step ----
    lwm(mkseg(preN, 256, 0, 0, 0, 256), segz(),
        wb, W_NI2, 256, niB2, 0, 0, hcmb1, VN, 128, 256, 0, 0, 0, 128, 0, 0, 1);
    lwm(mkseg(preE, 384, 0, 0, 0, 384), segz(),
        wb, W_EI2, 384, eiB2, 0, 0, ecmb, VE, 128, 384, 0, 0, 0, 128, 0, 0, 1);
    lwm(mkseg(ecmb, 128, 0, 0, 0, 128), segz(),
        wb, W_MSG3, 128, msgB, 0, 0, R1, VE, 256, 128, 0, 0, 0, 256, 0, 0);
    lwm(mkseg(hcmb1, 128, 0, 0, 0, 128), segz(),
        wb, W_AB, 128, 0, 0, 0, XW, VN, 512, 128, 0, 0, 0, 512, 0, 0);
    zero_k<<<1536, 256>>>(agg, VN * 256 / 4);
    scatter_agg<<<6144, 256>>>(XW, R1, fromi, toi, agg);
    lwm(mkseg(hcmb1, 128, 0, 0, 0, 128), mkseg(agg, 256, 0, 0, 128, 384),
        wb, W_NU1, 384, nuB1, 0, 0, hidu, VN, 256, 384, 1, 0, 0, 256, 0, 0);
    lwm(mkseg(hidu, 256, 0, 0, 0, 256), segz(),
        wb, W_NU2, 256, nuB2, 0, 0, upN + 128, VN, 128, 256, 0, 48, 64, 768, 0, 0);
    lwm(mkseg(upN + 128, 768, 48, 64, 0, 128), segz(),
        wb, W_SUM, 128, 0, 0, 0, Y, VN, 256, 128, 0, 0, 0, 256, 0, 0);
    msgs_k<<<6144, 256>>>(Y, R1, fromi, toi, upE + 256, agg);

    for (int k = 0; k < 3; k++) {
        for (int p = 2; p <= 5; p++) {
            // node combine
            if (k == 0) {
                lwm(mkseg(upN + (size_t)(p - 1) * 128, 768, 48, 64, 0, 128), segz(),
                    wb, W_NI1, 256, niB1, 0, 0, hidn, VN, 256, 128, 1, 0, 0, 256, 0, 0);
            } else {
                lwm(mkseg(upN + (size_t)(p - 1) * 128, 768, 48, 64, 0, 128),
                    mkseg(stN + (size_t)(p - 1) * 128, 768, 48, 64, 128, 256),
                    wb, W_NI1, 256, niB1, 0, 0, hidn, VN, 256, 256, 1, 0, 0, 256, 0, 0);
            }
            lwm(mkseg(hidn, 256, 0, 0, 0, 256), segz(),
                wb, W_NI2, 256, niB2, 0, 0, hcmb, VN, 128, 256, 0, 0, 0, 128, 0, 0);
            // edge combine + R (k-invariant at k==0: reuse R1)
            const float* Rp = R1;
            if (k > 0) {
                lwm(mkseg(stE + (size_t)(p - 1) * 256, 1536, 192, 256, 0, 256), segz(),
                    wb, W_EI1 + 128, 384, 0, preE, 384, hide, VE, 384, 256, 1, 0, 0, 384, 0, 0);
                lwm(mkseg(hide, 384, 0, 0, 0, 384), segz(),
                    wb, W_EI2, 384, eiB2, 0, 0, ecmb, VE, 128, 384, 0, 0, 0, 128, 0, 0);
                lwm(mkseg(ecmb, 128, 0, 0, 0, 128), segz(),
                    wb, W_MSG3, 128, msgB, 0, 0, R, VE, 256, 128, 0, 0, 0, 256, 0, 0);
                Rp = R;
            }
            // XW = hcmb @ [W1|W2] ; aggregate (agg pre-zeroed by previous msgs_k)
            lwm(mkseg(hcmb, 128, 0, 0, 0, 128), segz(),
                wb, W_AB, 128, 0, 0, 0, XW, VN, 512, 128, 0, 0, 0, 512, 0, 0);
            scatter_agg<<<6144, 256>>>(XW, Rp, fromi, toi, agg);
            // node update -> upN slot p
            lwm(mkseg(hcmb, 128, 0, 0, 0, 128), mkseg(agg, 256, 0, 0, 128, 384),
                wb, W_NU1, 384, nuB1, 0, 0, hidu, VN, 256, 384, 1, 0, 0, 256, 0, 0);
            lwm(mkseg(hidu, 256, 0, 0, 0, 256), segz(),
                wb, W_NU2, 256, nuB2, 0, 0, upN + (size_t)p * 128,
                VN, 128, 256, 0, 48, 64, 768, 0, 0);
            // Y = h_p @ (W1+W2) ; msgs -> upE slot p (also zeroes agg for next step)
            lwm(mkseg(upN + (size_t)p * 128, 768, 48, 64, 0, 128), segz(),
                wb, W_SUM, 128, 0, 0, 0, Y, VN, 256, 128, 0, 0, 0, 256, 0, 0);
            msgs_k<<<6144, 256>>>(Y, Rp, fromi, toi, upE + (size_t)p * 256, agg);
        }

        // ================= node transport =================
        lwm(mkseg(upN + 640, 768, 0, 0, 0, 128), segz(),
            wb, W_NS1, 128, nsB1, 0, 0, tmp, 8192, 64, 128, 1, 0, 0, 64, 0, 0);
        lwm(mkseg(tmp, 64, 0, 0, 0, 64), segz(),
            wb, W_NS2, 64, nsB2, 0, 0, tqc, 8192, 64, 64, 0, 0, 0, 64, 64, 48);
        lbat(tqc, 8192, 64, 0, tqc + 4096, 8192, 64, 1, la, 4096, 64, 64, 64, 64, 10.0f, 64);
        sink_node<<<64, 256>>>(la);
        if (k < 2) {
            lbw(la, 4096, 64, 0, upN + 49152 + 128, 98304, 768, 0,
                stN + 128, 98304, 768, 64, 512, 64, 1.0f, 64);
            lbw(la, 4096, 64, 1, upN + 128, 98304, 768, 0,
                stN + 49152 + 128, 98304, 768, 64, 512, 64, 1.0f, 64);
        } else {
            lbw(la, 4096, 64, 0, upN + 49152 + 640, 98304, 768, 0,
                pq, 8192, 128, 64, 128, 64, 1.0f, 64);
        }

        // ================= edge transport (dead at k==2) =================
        if (k < 2) {
            lwm(mkseg(upE + 1280, 1536, 0, 0, 0, 256), segz(),
                wb, W_ES1, 256, esB1, 0, 0, tmp, 32768, 64, 256, 1, 0, 0, 64, 0, 0);
            lwm(mkseg(tmp, 64, 0, 0, 0, 64), segz(),
                wb, W_ES2, 64, esB2, 0, 0, tqc, 32768, 64, 64, 0, 0, 0, 64, 256, 192);
            lbat(tqc, 32768, 64, 0, tqc + 16384, 32768, 64, 1, la, 65536, 256,
                 256, 256, 64, 10.0f, 64);
            sink_edge<<<128, 256, SE_SMEM>>>(la);
            lbw(la, 65536, 256, 0, upE + 393216 + 256, 786432, 1536, 0,
                stE + 256, 786432, 1536, 256, 1024, 256, 1.0f, 64);
            lbw(la, 65536, 256, 1, upE + 256, 786432, 1536, 0,
                stE + 393216 + 256, 786432, 1536, 256, 1024, 256, 1.0f, 64);
        }
    }

    score_k<<<64, 256>>>(upN, pq, out);
    (void)in_sizes; (void)n_in; (void)out_size;
}